// round 12
// baseline (speedup 1.0000x reference)
#include <cuda_runtime.h>
#include <math.h>

#define NROW 4096
#define DDIM 64

// ---------------- device scratch (no allocations allowed) ----------------
static __device__ float        g_xx[(long long)NROW * NROW];   // 64 MB dist(x,x)
static __device__ float        g_yy[(long long)NROW * NROW];   // 64 MB dist(y,y)
static __device__ float        g_zz[(long long)NROW * NROW];   // 64 MB dist(x,y)
static __device__ float        g_cand[(long long)NROW * NROW]; // FULL-SIZE candidate buffer
static __device__ unsigned int g_ncand;
static __device__ float        g_norms[2][NROW];               // row norms of x, y
static __device__ float        g_rows[3][NROW];                // stage-A f32 row sums
static __device__ float        g_S[3];                         // stage-B f32 sums
static __device__ unsigned int g_h0[2048];
static __device__ unsigned int g_h1[2048];
static __device__ unsigned int g_h2[1024];
static __device__ unsigned int g_pfx0, g_pfx1, g_rank;
static __device__ float        g_par[8];   // [0..4]=s_k, [5]=fast-chain flag

#define CAND_CAP ((unsigned int)((long long)NROW * NROW))

// device-side selector (never pass __device__ symbols from host code)
__device__ __forceinline__ float* mat_of(int slot) {
    return (slot == 0) ? g_xx : (slot == 1) ? g_yy : g_zz;
}

// ---------------- helpers ----------------
// Cephes-style minimax expf (~1 ulp). Proven: rel_err == 0.0 end-to-end.
__device__ __forceinline__ float my_exp(float x) {
    x = fmaxf(x, -87.0f);
    float z = floorf(fmaf(x, 1.44269504088896341f, 0.5f));
    float r = fmaf(z, -0.693359375f, x);
    r = fmaf(z, 2.12194440e-4f, r);
    int n = (int)z;
    float p = 1.9875691500e-4f;
    p = fmaf(p, r, 1.3981999507e-3f);
    p = fmaf(p, r, 8.3334519073e-3f);
    p = fmaf(p, r, 4.1665795894e-2f);
    p = fmaf(p, r, 1.6666665459e-1f);
    p = fmaf(p, r, 5.0000001201e-1f);
    float res = fmaf(p, r * r, r) + 1.0f;
    return res * __int_as_float((n + 127) << 23);
}

// exact-replica 5-exp kernel mean: ((((e0+e1)+e2)+e3)+e4) / 5.0f
__device__ __forceinline__ float kmean5(float d, float s0, float s1, float s2,
                                        float s3, float s4) {
    float s = my_exp(d * s0);
    s = s + my_exp(d * s1);
    s = s + my_exp(d * s2);
    s = s + my_exp(d * s3);
    s = s + my_exp(d * s4);
    return s / 5.0f;
}

// fast chain (valid when s_{k+1} == 2*s_k exactly): 2 exps + 3 muls.
__device__ __forceinline__ float kmean5f(float d, float s0) {
    float v  = d * s0;
    float e0 = my_exp(v);
    float e2 = my_exp(4.0f * v);
    float e1 = e0 * e0;      // exp(2v)
    float e3 = e2 * e2;      // exp(8v)
    float e4 = e3 * e3;      // exp(16v)
    float s = e0 + e1;
    s = s + e2;
    s = s + e3;
    s = s + e4;
    return s / 5.0f;
}

// monotone key transform for float radix select
__device__ __forceinline__ unsigned int fkey(float f) {
    unsigned int b = __float_as_uint(f);
    return b ^ ((b & 0x80000000u) ? 0xffffffffu : 0x80000000u);
}

// warp-aggregated shared histogram add with weight
__device__ __forceinline__ void haddw(unsigned int* sh, unsigned int bin,
                                      unsigned int w) {
    unsigned int m = __match_any_sync(0xffffffffu, bin);
    if ((int)(threadIdx.x & 31u) == (int)(__ffs(m) - 1))
        atomicAdd(&sh[bin], (unsigned int)__popc(m) * w);
}

// ---------------- kernels ----------------
__global__ void k_init() {
    int t = threadIdx.x;
    for (int i = t; i < 2048; i += 256) { g_h0[i] = 0u; g_h1[i] = 0u; }
    for (int i = t; i < 1024; i += 256) g_h2[i] = 0u;
    if (t == 0) {
        g_rank = 8388607u;  // (N*N - 1) / 2 : lower-median rank
        g_pfx0 = 0u; g_pfx1 = 0u;
        g_ncand = 0u;
    }
}

// merged row norms: blockIdx.y selects x (0) or y (1)
__global__ void k_rownorm(const float* __restrict__ x, const float* __restrict__ y) {
    int which = blockIdx.y;
    const float* a = which ? y : x;
    int row  = blockIdx.x * 8 + (threadIdx.x >> 5);
    int lane = threadIdx.x & 31;
    float v0 = a[row * DDIM + lane];
    float v1 = a[row * DDIM + 32 + lane];
    float s  = v0 * v0 + v1 * v1;
#pragma unroll
    for (int o = 16; o > 0; o >>= 1) s += __shfl_down_sync(0xffffffffu, s, o);
    if (lane == 0) g_norms[which][row] = s;
}

// 128x128 tile, 256 threads, 8x8/thread, K=64. Symmetry-aware, bit-exact
// mirror for xx/yy off-diagonal blocks (transposed smem staging). xx blocks
// additionally build the pass-0 median histogram in-register (weight 2 on
// mirrored blocks) — integer-exact, replaces the hist0 sweep.
// Linear grid: [0,528)=xx tri, [528,1056)=yy tri, [1056,2080)=zz full.
__global__ void __launch_bounds__(256, 2) k_tile128(const float* __restrict__ x,
                                                    const float* __restrict__ y) {
    extern __shared__ float sm[];
    float* As = sm;             // [128][69]
    float* Bs = sm + 128 * 69;  // [128][69]
    __shared__ unsigned int sh_hist[2048];

    int idx = blockIdx.x;
    int z, bxb, byb;
    if (idx < 1056) {
        z = (idx < 528) ? 0 : 1;
        int t = idx - z * 528;
        int by = (int)((sqrtf(8.0f * (float)t + 1.0f) - 1.0f) * 0.5f);
        while (by * (by + 1) / 2 > t) by--;
        while ((by + 1) * (by + 2) / 2 <= t) by++;
        byb = by;
        bxb = t - by * (by + 1) / 2;     // bxb <= byb
    } else {
        z = 2;
        int t = idx - 1056;
        bxb = t & 31;
        byb = t >> 5;
    }

    const float* A = (z == 1) ? y : x;
    const float* B = (z == 0) ? x : y;
    const int anw = (z == 1) ? 1 : 0;
    const int bnw = (z == 0) ? 0 : 1;
    float* OUT = mat_of(z);

    const int bm  = byb * 128;
    const int bc  = bxb * 128;
    const int tid = threadIdx.x;

    if (z == 0) {
#pragma unroll
        for (int i = tid; i < 2048; i += 256) sh_hist[i] = 0u;
    }

    const float4* Ag = reinterpret_cast<const float4*>(A + (long long)bm * DDIM);
    const float4* Bg = reinterpret_cast<const float4*>(B + (long long)bc * DDIM);
#pragma unroll
    for (int i = tid; i < 2048; i += 256) {
        int row = i >> 4, f4 = i & 15;
        float4 va = Ag[row * 16 + f4];
        float4 vb = Bg[row * 16 + f4];
        int c4 = f4 * 4;
        As[row * 69 + c4 + 0] = va.x; As[row * 69 + c4 + 1] = va.y;
        As[row * 69 + c4 + 2] = va.z; As[row * 69 + c4 + 3] = va.w;
        Bs[row * 69 + c4 + 0] = vb.x; Bs[row * 69 + c4 + 1] = vb.y;
        Bs[row * 69 + c4 + 2] = vb.z; Bs[row * 69 + c4 + 3] = vb.w;
    }
    __syncthreads();

    const int tx = tid & 15, ty = tid >> 4;

    int arow[8], brow[8];
#pragma unroll
    for (int i = 0; i < 8; i++) arow[i] = (ty + 16 * i) * 69;
#pragma unroll
    for (int j = 0; j < 8; j++)
        brow[j] = (2 * tx + 32 * (j >> 1) + (j & 1)) * 69;

    float acc[8][8];
#pragma unroll
    for (int i = 0; i < 8; i++)
#pragma unroll
        for (int j = 0; j < 8; j++) acc[i][j] = 0.0f;

    float a0[8], b0[8], a1[8], b1[8];
#pragma unroll
    for (int i = 0; i < 8; i++) a0[i] = As[arow[i]];
#pragma unroll
    for (int j = 0; j < 8; j++) b0[j] = Bs[brow[j]];

#pragma unroll 4
    for (int k = 0; k < 64; k += 2) {
#pragma unroll
        for (int i = 0; i < 8; i++) a1[i] = As[arow[i] + k + 1];
#pragma unroll
        for (int j = 0; j < 8; j++) b1[j] = Bs[brow[j] + k + 1];
#pragma unroll
        for (int i = 0; i < 8; i++)
#pragma unroll
            for (int j = 0; j < 8; j++)
                acc[i][j] = fmaf(a0[i], b0[j], acc[i][j]);
#pragma unroll
        for (int i = 0; i < 8; i++) a0[i] = As[arow[i] + k + 2];  // k=62 -> pad col
#pragma unroll
        for (int j = 0; j < 8; j++) b0[j] = Bs[brow[j] + k + 2];
#pragma unroll
        for (int i = 0; i < 8; i++)
#pragma unroll
            for (int j = 0; j < 8; j++)
                acc[i][j] = fmaf(a1[i], b1[j], acc[i][j]);
    }

    const float* an = g_norms[anw];
    const float* bn = g_norms[bnw];
    const bool mirror = (z < 2) && (bm != bc);
    const unsigned int hw = mirror ? 2u : 1u;   // hist weight (xx only)
    float* T = sm;  // transposed staging [128][129] — reuses As/Bs space

    if (mirror) __syncthreads();   // k-loop smem reads complete before overwrite

#pragma unroll
    for (int i = 0; i < 8; i++) {
        int rl = ty + 16 * i;
        int r  = bm + rl;
        float base2 = an[r];
#pragma unroll
        for (int h = 0; h < 4; h++) {
            int cl = 2 * tx + 32 * h;
            int c  = bc + cl;
            float2 o;
            o.x = fmaf(-2.0f, acc[i][2 * h + 0], base2 + bn[c + 0]);
            o.y = fmaf(-2.0f, acc[i][2 * h + 1], base2 + bn[c + 1]);
            *reinterpret_cast<float2*>(&OUT[(long long)r * NROW + c]) = o;
            if (mirror) {
                T[(cl + 0) * 129 + rl] = o.x;   // conflict-free: bank=2tx+ty(+1)
                T[(cl + 1) * 129 + rl] = o.y;
            }
            if (z == 0) {
                haddw(sh_hist, fkey(o.x) >> 21, hw);
                haddw(sh_hist, fkey(o.y) >> 21, hw);
            }
        }
    }

    if (mirror) {
        __syncthreads();
        int rr   = tid >> 1;
        int cb   = (tid & 1) * 64;
        long long obase = (long long)(bc + rr) * NROW + bm + cb;
#pragma unroll
        for (int v = 0; v < 16; v++) {
            float4 o;
            o.x = T[rr * 129 + cb + 4 * v + 0];
            o.y = T[rr * 129 + cb + 4 * v + 1];
            o.z = T[rr * 129 + cb + 4 * v + 2];
            o.w = T[rr * 129 + cb + 4 * v + 3];
            *reinterpret_cast<float4*>(&OUT[obase + 4 * v]) = o;
        }
    }

    if (z == 0) {
        __syncthreads();   // all hadds done
#pragma unroll
        for (int i = tid; i < 2048; i += 256) {
            unsigned int v = sh_hist[i];
            if (v) atomicAdd(&g_h0[i], v);
        }
    }
}

// ---- candidate compaction: collect elements whose top-11-bit key == pfx0 ----
__global__ void k_collect() {
    const unsigned int pfx = g_pfx0;
    const float4* p = reinterpret_cast<const float4*>(g_xx);
    unsigned int i = blockIdx.x * 256u + threadIdx.x;
    const unsigned int stride = 1024u * 256u;
    const int lane = threadIdx.x & 31;
    for (int it = 0; it < 16; it++, i += stride) {
        float4 v = p[i];
        float vals[4] = {v.x, v.y, v.z, v.w};
#pragma unroll
        for (int c = 0; c < 4; c++) {
            bool pred = ((fkey(vals[c]) >> 21) == pfx);
            unsigned int bal = __ballot_sync(0xffffffffu, pred);
            if (bal) {
                unsigned int base = 0;
                if (lane == 0) base = atomicAdd(&g_ncand, (unsigned int)__popc(bal));
                base = __shfl_sync(0xffffffffu, base, 0);
                if (pred) {
                    unsigned int pos = base + __popc(bal & ((1u << lane) - 1u));
                    if (pos < CAND_CAP) g_cand[pos] = vals[c];   // defensive clamp
                }
            }
        }
    }
}

// hist over candidates, bits [10,21)  (all candidates already match pfx0)
__global__ void k_hist1c() {
    __shared__ unsigned int sh[2048];
    for (int i = threadIdx.x; i < 2048; i += 256) sh[i] = 0u;
    __syncthreads();
    const unsigned int n = g_ncand;
    for (unsigned int i = blockIdx.x * 256u + threadIdx.x; i < n; i += 262144u) {
        unsigned int k = fkey(g_cand[i]);
        atomicAdd(&sh[(k >> 10) & 2047u], 1u);
    }
    __syncthreads();
    for (int i = threadIdx.x; i < 2048; i += 256) {
        unsigned int v = sh[i];
        if (v) atomicAdd(&g_h1[i], v);
    }
}

// hist over candidates matching pfx1, low 10 bits
__global__ void k_hist2c() {
    __shared__ unsigned int sh[1024];
    for (int i = threadIdx.x; i < 1024; i += 256) sh[i] = 0u;
    __syncthreads();
    const unsigned int pfx = g_pfx1;
    const unsigned int n = g_ncand;
    for (unsigned int i = blockIdx.x * 256u + threadIdx.x; i < n; i += 262144u) {
        unsigned int k = fkey(g_cand[i]);
        if ((k >> 10) == pfx) atomicAdd(&sh[k & 1023u], 1u);
    }
    __syncthreads();
    for (int i = threadIdx.x; i < 1024; i += 256) {
        unsigned int v = sh[i];
        if (v) atomicAdd(&g_h2[i], v);
    }
}

__global__ void k_select(int pass, const float* __restrict__ ks) {
    __shared__ unsigned int sh[2048];
    __shared__ unsigned int part[64];
    const unsigned int* hist = (pass == 0) ? g_h0 : (pass == 1) ? g_h1 : g_h2;
    const int nbins = (pass == 2) ? 1024 : 2048;
    const int per   = nbins / 64;
    const int tid   = threadIdx.x;  // 64 threads
    unsigned int s = 0;
    for (int i = 0; i < per; i++) {
        unsigned int v = hist[tid * per + i];
        sh[tid * per + i] = v;
        s += v;
    }
    part[tid] = s;
    __syncthreads();
    if (tid == 0) {
        unsigned int rank = g_rank, cum = 0;
        int seg = 0;
        while (seg < 63 && cum + part[seg] <= rank) { cum += part[seg]; seg++; }
        int b = seg * per;
        while (cum + sh[b] <= rank) { cum += sh[b]; b++; }
        g_rank = rank - cum;
        if (pass == 0) {
            g_pfx0 = (unsigned int)b;
        } else if (pass == 1) {
            g_pfx1 = (g_pfx0 << 11) | (unsigned int)b;
        } else {
            unsigned int key  = (g_pfx1 << 10) | (unsigned int)b;
            unsigned int bits = (key & 0x80000000u) ? (key ^ 0x80000000u) : ~key;
            float med  = __uint_as_float(bits);
            float base = -1.0f / med;
            float p0 = base * ks[0], p1 = base * ks[1], p2 = base * ks[2];
            float p3 = base * ks[3], p4 = base * ks[4];
            g_par[0] = p0; g_par[1] = p1; g_par[2] = p2; g_par[3] = p3; g_par[4] = p4;
            bool fast = (p1 == 2.0f * p0) && (p2 == 2.0f * p1) &&
                        (p3 == 2.0f * p2) && (p4 == 2.0f * p3);
            g_par[5] = fast ? 1.0f : 0.0f;
        }
    }
}

// Stage-A XLA row-reduction replica (bit-exact shape). grid=(4096, 3).
__global__ void __launch_bounds__(256) k_rowreduce() {
    __shared__ float ws[8];
    const int r    = blockIdx.x;
    const int slot = blockIdx.y;
    const int diagskip = (slot != 2) ? 1 : 0;
    const int t = threadIdx.x;
    float s0 = g_par[0], s1 = g_par[1], s2 = g_par[2], s3 = g_par[3], s4 = g_par[4];
    const bool fast = g_par[5] > 0.5f;
    const float* M = mat_of(slot);
    const float2* p = reinterpret_cast<const float2*>(M + (long long)r * NROW);

    float ax = 0.0f, ay = 0.0f;
    if (fast) {
#pragma unroll
        for (int i = 0; i < 8; i++) {
            float2 v = p[i * 256 + t];
            int c = (i * 256 + t) * 2;
            float kx = kmean5f(v.x, s0);
            float ky = kmean5f(v.y, s0);
            if (diagskip && c == r)     kx = 0.0f;
            if (diagskip && c + 1 == r) ky = 0.0f;
            ax += kx;
            ay += ky;
        }
    } else {
#pragma unroll
        for (int i = 0; i < 8; i++) {
            float2 v = p[i * 256 + t];
            int c = (i * 256 + t) * 2;
            float kx = (diagskip && c == r)     ? 0.0f : kmean5(v.x, s0, s1, s2, s3, s4);
            float ky = (diagskip && c + 1 == r) ? 0.0f : kmean5(v.y, s0, s1, s2, s3, s4);
            ax += kx;
            ay += ky;
        }
    }
    float v = ax + ay;
#pragma unroll
    for (int o = 16; o > 0; o >>= 1) v += __shfl_down_sync(0xffffffffu, v, o);
    if ((t & 31) == 0) ws[t >> 5] = v;
    __syncthreads();
    if (t < 32) {
        float w = (t < 8) ? ws[t] : 0.0f;
#pragma unroll
        for (int o = 16; o > 0; o >>= 1) w += __shfl_down_sync(0xffffffffu, w, o);
        if (t == 0) g_rows[slot][r] = w;
    }
}

// Stage-B: same reduce shape over the 4096 f32 row sums. grid=3.
__global__ void __launch_bounds__(256) k_stageB() {
    __shared__ float ws[8];
    const int slot = blockIdx.x;
    const int t = threadIdx.x;
    const float2* p = reinterpret_cast<const float2*>(g_rows[slot]);
    float ax = 0.0f, ay = 0.0f;
#pragma unroll
    for (int i = 0; i < 8; i++) {
        float2 v = p[i * 256 + t];
        ax += v.x;
        ay += v.y;
    }
    float v = ax + ay;
#pragma unroll
    for (int o = 16; o > 0; o >>= 1) v += __shfl_down_sync(0xffffffffu, v, o);
    if ((t & 31) == 0) ws[t >> 5] = v;
    __syncthreads();
    if (t < 32) {
        float w = (t < 8) ? ws[t] : 0.0f;
#pragma unroll
        for (int o = 16; o > 0; o >>= 1) w += __shfl_down_sync(0xffffffffu, w, o);
        if (t == 0) g_S[slot] = w;
    }
}

// Final combine replicating the reference's f32 arithmetic.
__global__ void k_fin(float* out) {
    float S1 = g_S[0], S2 = g_S[1], S3 = g_S[2];
    float od = (float)(1.0 / 16773120.0);        // 1/(4096*4095) in f32
    float t1 = od * S1;
    float t2 = od * S2;
    float m3 = S3 * (1.0f / 16777216.0f);        // exact power-of-two scale
    float t3 = 2.0f * m3;                        // exact
    out[0] = (t1 + t2) - t3;
}

// ---------------- entry ----------------
extern "C" void kernel_launch(void* const* d_in, const int* in_sizes, int n_in,
                              void* d_out, int out_size) {
    (void)in_sizes; (void)n_in; (void)out_size;
    const float* x  = (const float*)d_in[0];
    const float* y  = (const float*)d_in[1];
    const float* ks = (const float*)d_in[2];

    const int TILE_SMEM = 2 * 128 * 69 * (int)sizeof(float);  // 70656 B dynamic
    cudaFuncSetAttribute(k_tile128, cudaFuncAttributeMaxDynamicSharedMemorySize,
                         TILE_SMEM);

    k_init<<<1, 256>>>();
    dim3 rn(512, 2);
    k_rownorm<<<rn, 256>>>(x, y);

    // 528 (xx tri, +fused hist0) + 528 (yy tri) + 1024 (zz full) = 2080 blocks
    k_tile128<<<2080, 256, TILE_SMEM>>>(x, y);

    k_select<<<1, 64>>>(0, ks);          // pass-0 select (hist fused in tiles)
    k_collect<<<1024, 256>>>();          // compact pfx0 candidates
    k_hist1c<<<1024, 256>>>();
    k_select<<<1, 64>>>(1, ks);
    k_hist2c<<<1024, 256>>>();
    k_select<<<1, 64>>>(2, ks);          // -> median, scales, fast flag

    dim3 rg(4096, 3);
    k_rowreduce<<<rg, 256>>>();          // stage-A rows for all 3
    k_stageB<<<3, 256>>>();              // stage-B sums
    k_fin<<<1, 1>>>((float*)d_out);
}

// round 13
// speedup vs baseline: 2.1132x; 2.1132x over previous
#include <cuda_runtime.h>
#include <math.h>

#define NROW 4096
#define DDIM 64

// ---------------- device scratch (no allocations allowed) ----------------
static __device__ float        g_xx[(long long)NROW * NROW];   // 64 MB dist(x,x)
static __device__ float        g_yy[(long long)NROW * NROW];   // 64 MB dist(y,y)
static __device__ float        g_zz[(long long)NROW * NROW];   // 64 MB dist(x,y)
static __device__ float        g_norms[2][NROW];               // row norms of x, y
static __device__ float        g_rows[3][NROW];                // stage-A f32 row sums
static __device__ float        g_S[3];                         // stage-B f32 sums
static __device__ unsigned int g_h0[2048];
static __device__ unsigned int g_h1[2048];
static __device__ unsigned int g_h2[1024];
static __device__ unsigned int g_pfx0, g_pfx1, g_rank;
static __device__ float        g_par[8];   // [0..4]=s_k, [5]=fast-chain flag

// device-side selector (never pass __device__ symbols from host code)
__device__ __forceinline__ float* mat_of(int slot) {
    return (slot == 0) ? g_xx : (slot == 1) ? g_yy : g_zz;
}

// ---------------- helpers ----------------
// Cephes-style minimax expf (~1 ulp). Proven: rel_err == 0.0 end-to-end.
__device__ __forceinline__ float my_exp(float x) {
    x = fmaxf(x, -87.0f);
    float z = floorf(fmaf(x, 1.44269504088896341f, 0.5f));
    float r = fmaf(z, -0.693359375f, x);
    r = fmaf(z, 2.12194440e-4f, r);
    int n = (int)z;
    float p = 1.9875691500e-4f;
    p = fmaf(p, r, 1.3981999507e-3f);
    p = fmaf(p, r, 8.3334519073e-3f);
    p = fmaf(p, r, 4.1665795894e-2f);
    p = fmaf(p, r, 1.6666665459e-1f);
    p = fmaf(p, r, 5.0000001201e-1f);
    float res = fmaf(p, r * r, r) + 1.0f;
    return res * __int_as_float((n + 127) << 23);
}

// exact-replica 5-exp kernel mean: ((((e0+e1)+e2)+e3)+e4) / 5.0f
__device__ __forceinline__ float kmean5(float d, float s0, float s1, float s2,
                                        float s3, float s4) {
    float s = my_exp(d * s0);
    s = s + my_exp(d * s1);
    s = s + my_exp(d * s2);
    s = s + my_exp(d * s3);
    s = s + my_exp(d * s4);
    return s / 5.0f;
}

// fast chain (valid when s_{k+1} == 2*s_k exactly): 2 exps + 3 muls.
__device__ __forceinline__ float kmean5f(float d, float s0) {
    float v  = d * s0;
    float e0 = my_exp(v);
    float e2 = my_exp(4.0f * v);
    float e1 = e0 * e0;      // exp(2v)
    float e3 = e2 * e2;      // exp(8v)
    float e4 = e3 * e3;      // exp(16v)
    float s = e0 + e1;
    s = s + e2;
    s = s + e3;
    s = s + e4;
    return s / 5.0f;
}

// monotone key transform for float radix select
__device__ __forceinline__ unsigned int fkey(float f) {
    unsigned int b = __float_as_uint(f);
    return b ^ ((b & 0x80000000u) ? 0xffffffffu : 0x80000000u);
}

// warp-aggregated shared histogram add (weighted)
__device__ __forceinline__ void haddw(unsigned int* sh, unsigned int bin,
                                      unsigned int w) {
    unsigned int m = __match_any_sync(0xffffffffu, bin);
    if ((int)(threadIdx.x & 31u) == (int)(__ffs(m) - 1))
        atomicAdd(&sh[bin], (unsigned int)__popc(m) * w);
}

// ---------------- kernels ----------------
__global__ void k_init() {
    int t = threadIdx.x;
    for (int i = t; i < 2048; i += 256) { g_h0[i] = 0u; g_h1[i] = 0u; }
    for (int i = t; i < 1024; i += 256) g_h2[i] = 0u;
    if (t == 0) {
        g_rank = 8388607u;  // (N*N - 1) / 2 : lower-median rank
        g_pfx0 = 0u; g_pfx1 = 0u;
    }
}

// merged row norms: blockIdx.y selects x (0) or y (1)
__global__ void k_rownorm(const float* __restrict__ x, const float* __restrict__ y) {
    int which = blockIdx.y;
    const float* a = which ? y : x;
    int row  = blockIdx.x * 8 + (threadIdx.x >> 5);
    int lane = threadIdx.x & 31;
    float v0 = a[row * DDIM + lane];
    float v1 = a[row * DDIM + 32 + lane];
    float s  = v0 * v0 + v1 * v1;
#pragma unroll
    for (int o = 16; o > 0; o >>= 1) s += __shfl_down_sync(0xffffffffu, s, o);
    if (lane == 0) g_norms[which][row] = s;
}

// 128x128 tile, 256 threads, 8x8/thread, K=64. Symmetry-aware, bit-exact
// mirror for xx/yy off-diagonal blocks (transposed smem staging). xx blocks
// additionally build the pass-0 median histogram in-register (weight 2 on
// mirrored blocks) — integer-exact, replaces the hist0 sweep.
// Linear grid: [0,528)=xx tri, [528,1056)=yy tri, [1056,2080)=zz full.
__global__ void __launch_bounds__(256, 2) k_tile128(const float* __restrict__ x,
                                                    const float* __restrict__ y) {
    extern __shared__ float sm[];
    float* As = sm;             // [128][69]
    float* Bs = sm + 128 * 69;  // [128][69]
    __shared__ unsigned int sh_hist[2048];

    int idx = blockIdx.x;
    int z, bxb, byb;
    if (idx < 1056) {
        z = (idx < 528) ? 0 : 1;
        int t = idx - z * 528;
        int by = (int)((sqrtf(8.0f * (float)t + 1.0f) - 1.0f) * 0.5f);
        while (by * (by + 1) / 2 > t) by--;
        while ((by + 1) * (by + 2) / 2 <= t) by++;
        byb = by;
        bxb = t - by * (by + 1) / 2;     // bxb <= byb
    } else {
        z = 2;
        int t = idx - 1056;
        bxb = t & 31;
        byb = t >> 5;
    }

    const float* A = (z == 1) ? y : x;
    const float* B = (z == 0) ? x : y;
    const int anw = (z == 1) ? 1 : 0;
    const int bnw = (z == 0) ? 0 : 1;
    float* OUT = mat_of(z);

    const int bm  = byb * 128;
    const int bc  = bxb * 128;
    const int tid = threadIdx.x;

    if (z == 0) {
#pragma unroll
        for (int i = tid; i < 2048; i += 256) sh_hist[i] = 0u;
    }

    const float4* Ag = reinterpret_cast<const float4*>(A + (long long)bm * DDIM);
    const float4* Bg = reinterpret_cast<const float4*>(B + (long long)bc * DDIM);
#pragma unroll
    for (int i = tid; i < 2048; i += 256) {
        int row = i >> 4, f4 = i & 15;
        float4 va = Ag[row * 16 + f4];
        float4 vb = Bg[row * 16 + f4];
        int c4 = f4 * 4;
        As[row * 69 + c4 + 0] = va.x; As[row * 69 + c4 + 1] = va.y;
        As[row * 69 + c4 + 2] = va.z; As[row * 69 + c4 + 3] = va.w;
        Bs[row * 69 + c4 + 0] = vb.x; Bs[row * 69 + c4 + 1] = vb.y;
        Bs[row * 69 + c4 + 2] = vb.z; Bs[row * 69 + c4 + 3] = vb.w;
    }
    __syncthreads();

    const int tx = tid & 15, ty = tid >> 4;

    int arow[8], brow[8];
#pragma unroll
    for (int i = 0; i < 8; i++) arow[i] = (ty + 16 * i) * 69;
#pragma unroll
    for (int j = 0; j < 8; j++)
        brow[j] = (2 * tx + 32 * (j >> 1) + (j & 1)) * 69;

    float acc[8][8];
#pragma unroll
    for (int i = 0; i < 8; i++)
#pragma unroll
        for (int j = 0; j < 8; j++) acc[i][j] = 0.0f;

    float a0[8], b0[8], a1[8], b1[8];
#pragma unroll
    for (int i = 0; i < 8; i++) a0[i] = As[arow[i]];
#pragma unroll
    for (int j = 0; j < 8; j++) b0[j] = Bs[brow[j]];

#pragma unroll 4
    for (int k = 0; k < 64; k += 2) {
#pragma unroll
        for (int i = 0; i < 8; i++) a1[i] = As[arow[i] + k + 1];
#pragma unroll
        for (int j = 0; j < 8; j++) b1[j] = Bs[brow[j] + k + 1];
#pragma unroll
        for (int i = 0; i < 8; i++)
#pragma unroll
            for (int j = 0; j < 8; j++)
                acc[i][j] = fmaf(a0[i], b0[j], acc[i][j]);
#pragma unroll
        for (int i = 0; i < 8; i++) a0[i] = As[arow[i] + k + 2];  // k=62 -> pad col
#pragma unroll
        for (int j = 0; j < 8; j++) b0[j] = Bs[brow[j] + k + 2];
#pragma unroll
        for (int i = 0; i < 8; i++)
#pragma unroll
            for (int j = 0; j < 8; j++)
                acc[i][j] = fmaf(a1[i], b1[j], acc[i][j]);
    }

    const float* an = g_norms[anw];
    const float* bn = g_norms[bnw];
    const bool mirror = (z < 2) && (bm != bc);
    const unsigned int hw = mirror ? 2u : 1u;   // hist weight (xx only)
    float* T = sm;  // transposed staging [128][129] — reuses As/Bs space

    if (mirror) __syncthreads();   // k-loop smem reads complete before overwrite

#pragma unroll
    for (int i = 0; i < 8; i++) {
        int rl = ty + 16 * i;
        int r  = bm + rl;
        float base2 = an[r];
#pragma unroll
        for (int h = 0; h < 4; h++) {
            int cl = 2 * tx + 32 * h;
            int c  = bc + cl;
            float2 o;
            o.x = fmaf(-2.0f, acc[i][2 * h + 0], base2 + bn[c + 0]);
            o.y = fmaf(-2.0f, acc[i][2 * h + 1], base2 + bn[c + 1]);
            *reinterpret_cast<float2*>(&OUT[(long long)r * NROW + c]) = o;
            if (mirror) {
                T[(cl + 0) * 129 + rl] = o.x;   // conflict-free: bank=2tx+ty(+1)
                T[(cl + 1) * 129 + rl] = o.y;
            }
            if (z == 0) {
                haddw(sh_hist, fkey(o.x) >> 21, hw);
                haddw(sh_hist, fkey(o.y) >> 21, hw);
            }
        }
    }

    if (mirror) {
        __syncthreads();
        int rr   = tid >> 1;
        int cb   = (tid & 1) * 64;
        long long obase = (long long)(bc + rr) * NROW + bm + cb;
#pragma unroll
        for (int v = 0; v < 16; v++) {
            float4 o;
            o.x = T[rr * 129 + cb + 4 * v + 0];
            o.y = T[rr * 129 + cb + 4 * v + 1];
            o.z = T[rr * 129 + cb + 4 * v + 2];
            o.w = T[rr * 129 + cb + 4 * v + 3];
            *reinterpret_cast<float4*>(&OUT[obase + 4 * v]) = o;
        }
    }

    if (z == 0) {
        __syncthreads();   // all hadds done
#pragma unroll
        for (int i = tid; i < 2048; i += 256) {
            unsigned int v = sh_hist[i];
            if (v) atomicAdd(&g_h0[i], v);
        }
    }
}

// ---- radix-select passes 1 & 2: full linear sweeps over g_xx (no contention) ----
__global__ void k_hist1() {
    __shared__ unsigned int sh[2048];
    for (int i = threadIdx.x; i < 2048; i += 256) sh[i] = 0u;
    __syncthreads();
    const unsigned int pfx = g_pfx0;
    const float4* p = reinterpret_cast<const float4*>(g_xx);
    unsigned int i = blockIdx.x * 256u + threadIdx.x;
    const unsigned int stride = 1024u * 256u;
    for (int it = 0; it < 16; it++, i += stride) {
        float4 v = p[i];
        unsigned int k;
        k = fkey(v.x); if ((k >> 21) == pfx) atomicAdd(&sh[(k >> 10) & 2047u], 1u);
        k = fkey(v.y); if ((k >> 21) == pfx) atomicAdd(&sh[(k >> 10) & 2047u], 1u);
        k = fkey(v.z); if ((k >> 21) == pfx) atomicAdd(&sh[(k >> 10) & 2047u], 1u);
        k = fkey(v.w); if ((k >> 21) == pfx) atomicAdd(&sh[(k >> 10) & 2047u], 1u);
    }
    __syncthreads();
    for (int i2 = threadIdx.x; i2 < 2048; i2 += 256) {
        unsigned int v = sh[i2];
        if (v) atomicAdd(&g_h1[i2], v);
    }
}

__global__ void k_hist2() {
    __shared__ unsigned int sh[1024];
    for (int i = threadIdx.x; i < 1024; i += 256) sh[i] = 0u;
    __syncthreads();
    const unsigned int pfx = g_pfx1;
    const float4* p = reinterpret_cast<const float4*>(g_xx);
    unsigned int i = blockIdx.x * 256u + threadIdx.x;
    const unsigned int stride = 1024u * 256u;
    for (int it = 0; it < 16; it++, i += stride) {
        float4 v = p[i];
        unsigned int k;
        k = fkey(v.x); if ((k >> 10) == pfx) atomicAdd(&sh[k & 1023u], 1u);
        k = fkey(v.y); if ((k >> 10) == pfx) atomicAdd(&sh[k & 1023u], 1u);
        k = fkey(v.z); if ((k >> 10) == pfx) atomicAdd(&sh[k & 1023u], 1u);
        k = fkey(v.w); if ((k >> 10) == pfx) atomicAdd(&sh[k & 1023u], 1u);
    }
    __syncthreads();
    for (int i2 = threadIdx.x; i2 < 1024; i2 += 256) {
        unsigned int v = sh[i2];
        if (v) atomicAdd(&g_h2[i2], v);
    }
}

__global__ void k_select(int pass, const float* __restrict__ ks) {
    __shared__ unsigned int sh[2048];
    __shared__ unsigned int part[64];
    const unsigned int* hist = (pass == 0) ? g_h0 : (pass == 1) ? g_h1 : g_h2;
    const int nbins = (pass == 2) ? 1024 : 2048;
    const int per   = nbins / 64;
    const int tid   = threadIdx.x;  // 64 threads
    unsigned int s = 0;
    for (int i = 0; i < per; i++) {
        unsigned int v = hist[tid * per + i];
        sh[tid * per + i] = v;
        s += v;
    }
    part[tid] = s;
    __syncthreads();
    if (tid == 0) {
        unsigned int rank = g_rank, cum = 0;
        int seg = 0;
        while (seg < 63 && cum + part[seg] <= rank) { cum += part[seg]; seg++; }
        int b = seg * per;
        while (cum + sh[b] <= rank) { cum += sh[b]; b++; }
        g_rank = rank - cum;
        if (pass == 0) {
            g_pfx0 = (unsigned int)b;
        } else if (pass == 1) {
            g_pfx1 = (g_pfx0 << 11) | (unsigned int)b;
        } else {
            unsigned int key  = (g_pfx1 << 10) | (unsigned int)b;
            unsigned int bits = (key & 0x80000000u) ? (key ^ 0x80000000u) : ~key;
            float med  = __uint_as_float(bits);
            float base = -1.0f / med;
            float p0 = base * ks[0], p1 = base * ks[1], p2 = base * ks[2];
            float p3 = base * ks[3], p4 = base * ks[4];
            g_par[0] = p0; g_par[1] = p1; g_par[2] = p2; g_par[3] = p3; g_par[4] = p4;
            bool fast = (p1 == 2.0f * p0) && (p2 == 2.0f * p1) &&
                        (p3 == 2.0f * p2) && (p4 == 2.0f * p3);
            g_par[5] = fast ? 1.0f : 0.0f;
        }
    }
}

// Stage-A XLA row-reduction replica (bit-exact shape). grid=(4096, 3).
__global__ void __launch_bounds__(256) k_rowreduce() {
    __shared__ float ws[8];
    const int r    = blockIdx.x;
    const int slot = blockIdx.y;
    const int diagskip = (slot != 2) ? 1 : 0;
    const int t = threadIdx.x;
    float s0 = g_par[0], s1 = g_par[1], s2 = g_par[2], s3 = g_par[3], s4 = g_par[4];
    const bool fast = g_par[5] > 0.5f;
    const float* M = mat_of(slot);
    const float2* p = reinterpret_cast<const float2*>(M + (long long)r * NROW);

    float ax = 0.0f, ay = 0.0f;
    if (fast) {
#pragma unroll
        for (int i = 0; i < 8; i++) {
            float2 v = p[i * 256 + t];
            int c = (i * 256 + t) * 2;
            float kx = kmean5f(v.x, s0);
            float ky = kmean5f(v.y, s0);
            if (diagskip && c == r)     kx = 0.0f;
            if (diagskip && c + 1 == r) ky = 0.0f;
            ax += kx;
            ay += ky;
        }
    } else {
#pragma unroll
        for (int i = 0; i < 8; i++) {
            float2 v = p[i * 256 + t];
            int c = (i * 256 + t) * 2;
            float kx = (diagskip && c == r)     ? 0.0f : kmean5(v.x, s0, s1, s2, s3, s4);
            float ky = (diagskip && c + 1 == r) ? 0.0f : kmean5(v.y, s0, s1, s2, s3, s4);
            ax += kx;
            ay += ky;
        }
    }
    float v = ax + ay;
#pragma unroll
    for (int o = 16; o > 0; o >>= 1) v += __shfl_down_sync(0xffffffffu, v, o);
    if ((t & 31) == 0) ws[t >> 5] = v;
    __syncthreads();
    if (t < 32) {
        float w = (t < 8) ? ws[t] : 0.0f;
#pragma unroll
        for (int o = 16; o > 0; o >>= 1) w += __shfl_down_sync(0xffffffffu, w, o);
        if (t == 0) g_rows[slot][r] = w;
    }
}

// Stage-B: same reduce shape over the 4096 f32 row sums. grid=3.
__global__ void __launch_bounds__(256) k_stageB() {
    __shared__ float ws[8];
    const int slot = blockIdx.x;
    const int t = threadIdx.x;
    const float2* p = reinterpret_cast<const float2*>(g_rows[slot]);
    float ax = 0.0f, ay = 0.0f;
#pragma unroll
    for (int i = 0; i < 8; i++) {
        float2 v = p[i * 256 + t];
        ax += v.x;
        ay += v.y;
    }
    float v = ax + ay;
#pragma unroll
    for (int o = 16; o > 0; o >>= 1) v += __shfl_down_sync(0xffffffffu, v, o);
    if ((t & 31) == 0) ws[t >> 5] = v;
    __syncthreads();
    if (t < 32) {
        float w = (t < 8) ? ws[t] : 0.0f;
#pragma unroll
        for (int o = 16; o > 0; o >>= 1) w += __shfl_down_sync(0xffffffffu, w, o);
        if (t == 0) g_S[slot] = w;
    }
}

// Final combine replicating the reference's f32 arithmetic.
__global__ void k_fin(float* out) {
    float S1 = g_S[0], S2 = g_S[1], S3 = g_S[2];
    float od = (float)(1.0 / 16773120.0);        // 1/(4096*4095) in f32
    float t1 = od * S1;
    float t2 = od * S2;
    float m3 = S3 * (1.0f / 16777216.0f);        // exact power-of-two scale
    float t3 = 2.0f * m3;                        // exact
    out[0] = (t1 + t2) - t3;
}

// ---------------- entry ----------------
extern "C" void kernel_launch(void* const* d_in, const int* in_sizes, int n_in,
                              void* d_out, int out_size) {
    (void)in_sizes; (void)n_in; (void)out_size;
    const float* x  = (const float*)d_in[0];
    const float* y  = (const float*)d_in[1];
    const float* ks = (const float*)d_in[2];

    const int TILE_SMEM = 2 * 128 * 69 * (int)sizeof(float);  // 70656 B dynamic
    cudaFuncSetAttribute(k_tile128, cudaFuncAttributeMaxDynamicSharedMemorySize,
                         TILE_SMEM);

    k_init<<<1, 256>>>();
    dim3 rn(512, 2);
    k_rownorm<<<rn, 256>>>(x, y);

    // 528 (xx tri, +fused hist0) + 528 (yy tri) + 1024 (zz full) = 2080 blocks
    k_tile128<<<2080, 256, TILE_SMEM>>>(x, y);

    k_select<<<1, 64>>>(0, ks);          // pass-0 select (hist fused in tiles)
    k_hist1<<<1024, 256>>>();
    k_select<<<1, 64>>>(1, ks);
    k_hist2<<<1024, 256>>>();
    k_select<<<1, 64>>>(2, ks);          // -> median, scales, fast flag

    dim3 rg(4096, 3);
    k_rowreduce<<<rg, 256>>>();          // stage-A rows for all 3
    k_stageB<<<3, 256>>>();              // stage-B sums
    k_fin<<<1, 1>>>((float*)d_out);
}

// round 14
// speedup vs baseline: 2.1569x; 1.0207x over previous
#include <cuda_runtime.h>
#include <math.h>

#define NROW 4096
#define DDIM 64

// ---------------- device scratch (no allocations allowed) ----------------
static __device__ float        g_xx[(long long)NROW * NROW];   // 64 MB dist(x,x)
static __device__ float        g_yy[(long long)NROW * NROW];   // 64 MB dist(y,y)
static __device__ float        g_zz[(long long)NROW * NROW];   // 64 MB dist(x,y)
static __device__ float        g_norms[2][NROW];               // row norms of x, y
static __device__ float        g_rows[3][NROW];                // stage-A f32 row sums
static __device__ float        g_S[3];                         // stage-B f32 sums
static __device__ unsigned int g_h0[2048];
static __device__ unsigned int g_h1[2048];
static __device__ unsigned int g_h2[1024];
static __device__ unsigned int g_pfx0, g_pfx1, g_rank;
static __device__ unsigned int g_done;
static __device__ float        g_par[8];   // [0..4]=s_k, [5]=fast-chain flag

// device-side selector (never pass __device__ symbols from host code)
__device__ __forceinline__ float* mat_of(int slot) {
    return (slot == 0) ? g_xx : (slot == 1) ? g_yy : g_zz;
}

// ---------------- helpers ----------------
// Cephes-style minimax expf (~1 ulp). Proven: rel_err == 0.0 end-to-end.
__device__ __forceinline__ float my_exp(float x) {
    x = fmaxf(x, -87.0f);
    float z = floorf(fmaf(x, 1.44269504088896341f, 0.5f));
    float r = fmaf(z, -0.693359375f, x);
    r = fmaf(z, 2.12194440e-4f, r);
    int n = (int)z;
    float p = 1.9875691500e-4f;
    p = fmaf(p, r, 1.3981999507e-3f);
    p = fmaf(p, r, 8.3334519073e-3f);
    p = fmaf(p, r, 4.1665795894e-2f);
    p = fmaf(p, r, 1.6666665459e-1f);
    p = fmaf(p, r, 5.0000001201e-1f);
    float res = fmaf(p, r * r, r) + 1.0f;
    return res * __int_as_float((n + 127) << 23);
}

// exact-replica 5-exp kernel mean: ((((e0+e1)+e2)+e3)+e4) / 5.0f
__device__ __forceinline__ float kmean5(float d, float s0, float s1, float s2,
                                        float s3, float s4) {
    float s = my_exp(d * s0);
    s = s + my_exp(d * s1);
    s = s + my_exp(d * s2);
    s = s + my_exp(d * s3);
    s = s + my_exp(d * s4);
    return s / 5.0f;
}

// fast chain (valid when s_{k+1} == 2*s_k exactly): 2 exps + 3 muls.
__device__ __forceinline__ float kmean5f(float d, float s0) {
    float v  = d * s0;
    float e0 = my_exp(v);
    float e2 = my_exp(4.0f * v);
    float e1 = e0 * e0;      // exp(2v)
    float e3 = e2 * e2;      // exp(8v)
    float e4 = e3 * e3;      // exp(16v)
    float s = e0 + e1;
    s = s + e2;
    s = s + e3;
    s = s + e4;
    return s / 5.0f;
}

// monotone key transform for float radix select
__device__ __forceinline__ unsigned int fkey(float f) {
    unsigned int b = __float_as_uint(f);
    return b ^ ((b & 0x80000000u) ? 0xffffffffu : 0x80000000u);
}

// warp-aggregated shared histogram add (weighted)
__device__ __forceinline__ void haddw(unsigned int* sh, unsigned int bin,
                                      unsigned int w) {
    unsigned int m = __match_any_sync(0xffffffffu, bin);
    if ((int)(threadIdx.x & 31u) == (int)(__ffs(m) - 1))
        atomicAdd(&sh[bin], (unsigned int)__popc(m) * w);
}

// ---------------- kernels ----------------
__global__ void k_init() {
    int t = threadIdx.x;
    for (int i = t; i < 2048; i += 256) { g_h0[i] = 0u; g_h1[i] = 0u; }
    for (int i = t; i < 1024; i += 256) g_h2[i] = 0u;
    if (t == 0) {
        g_rank = 8388607u;  // (N*N - 1) / 2 : lower-median rank
        g_pfx0 = 0u; g_pfx1 = 0u;
        g_done = 0u;
    }
}

// merged row norms: blockIdx.y selects x (0) or y (1)
__global__ void k_rownorm(const float* __restrict__ x, const float* __restrict__ y) {
    int which = blockIdx.y;
    const float* a = which ? y : x;
    int row  = blockIdx.x * 8 + (threadIdx.x >> 5);
    int lane = threadIdx.x & 31;
    float v0 = a[row * DDIM + lane];
    float v1 = a[row * DDIM + 32 + lane];
    float s  = v0 * v0 + v1 * v1;
#pragma unroll
    for (int o = 16; o > 0; o >>= 1) s += __shfl_down_sync(0xffffffffu, s, o);
    if (lane == 0) g_norms[which][row] = s;
}

// 128x128 tile, 256 threads, 8x8/thread, K=64. Symmetry-aware, bit-exact
// mirror for xx/yy off-diagonal blocks (transposed smem staging). xx blocks
// additionally build the pass-0 median histogram (weight 2 on mirrored
// blocks) — integer-exact, replaces the hist0 sweep.
// Linear grid: [0,528)=xx tri, [528,1056)=yy tri, [1056,2080)=zz full.
__global__ void __launch_bounds__(256, 2) k_tile128(const float* __restrict__ x,
                                                    const float* __restrict__ y) {
    extern __shared__ float sm[];
    float* As = sm;             // [128][69]
    float* Bs = sm + 128 * 69;  // [128][69]
    __shared__ unsigned int sh_hist[2048];

    int idx = blockIdx.x;
    int z, bxb, byb;
    if (idx < 1056) {
        z = (idx < 528) ? 0 : 1;
        int t = idx - z * 528;
        int by = (int)((sqrtf(8.0f * (float)t + 1.0f) - 1.0f) * 0.5f);
        while (by * (by + 1) / 2 > t) by--;
        while ((by + 1) * (by + 2) / 2 <= t) by++;
        byb = by;
        bxb = t - by * (by + 1) / 2;     // bxb <= byb
    } else {
        z = 2;
        int t = idx - 1056;
        bxb = t & 31;
        byb = t >> 5;
    }

    const float* A = (z == 1) ? y : x;
    const float* B = (z == 0) ? x : y;
    const int anw = (z == 1) ? 1 : 0;
    const int bnw = (z == 0) ? 0 : 1;
    float* OUT = mat_of(z);

    const int bm  = byb * 128;
    const int bc  = bxb * 128;
    const int tid = threadIdx.x;

    if (z == 0) {
#pragma unroll
        for (int i = tid; i < 2048; i += 256) sh_hist[i] = 0u;
    }

    const float4* Ag = reinterpret_cast<const float4*>(A + (long long)bm * DDIM);
    const float4* Bg = reinterpret_cast<const float4*>(B + (long long)bc * DDIM);
#pragma unroll
    for (int i = tid; i < 2048; i += 256) {
        int row = i >> 4, f4 = i & 15;
        float4 va = Ag[row * 16 + f4];
        float4 vb = Bg[row * 16 + f4];
        int c4 = f4 * 4;
        As[row * 69 + c4 + 0] = va.x; As[row * 69 + c4 + 1] = va.y;
        As[row * 69 + c4 + 2] = va.z; As[row * 69 + c4 + 3] = va.w;
        Bs[row * 69 + c4 + 0] = vb.x; Bs[row * 69 + c4 + 1] = vb.y;
        Bs[row * 69 + c4 + 2] = vb.z; Bs[row * 69 + c4 + 3] = vb.w;
    }
    __syncthreads();

    const int tx = tid & 15, ty = tid >> 4;

    int arow[8], brow[8];
#pragma unroll
    for (int i = 0; i < 8; i++) arow[i] = (ty + 16 * i) * 69;
#pragma unroll
    for (int j = 0; j < 8; j++)
        brow[j] = (2 * tx + 32 * (j >> 1) + (j & 1)) * 69;

    float acc[8][8];
#pragma unroll
    for (int i = 0; i < 8; i++)
#pragma unroll
        for (int j = 0; j < 8; j++) acc[i][j] = 0.0f;

    float a0[8], b0[8], a1[8], b1[8];
#pragma unroll
    for (int i = 0; i < 8; i++) a0[i] = As[arow[i]];
#pragma unroll
    for (int j = 0; j < 8; j++) b0[j] = Bs[brow[j]];

#pragma unroll 4
    for (int k = 0; k < 64; k += 2) {
#pragma unroll
        for (int i = 0; i < 8; i++) a1[i] = As[arow[i] + k + 1];
#pragma unroll
        for (int j = 0; j < 8; j++) b1[j] = Bs[brow[j] + k + 1];
#pragma unroll
        for (int i = 0; i < 8; i++)
#pragma unroll
            for (int j = 0; j < 8; j++)
                acc[i][j] = fmaf(a0[i], b0[j], acc[i][j]);
#pragma unroll
        for (int i = 0; i < 8; i++) a0[i] = As[arow[i] + k + 2];  // k=62 -> pad col
#pragma unroll
        for (int j = 0; j < 8; j++) b0[j] = Bs[brow[j] + k + 2];
#pragma unroll
        for (int i = 0; i < 8; i++)
#pragma unroll
            for (int j = 0; j < 8; j++)
                acc[i][j] = fmaf(a1[i], b1[j], acc[i][j]);
    }

    const float* an = g_norms[anw];
    const float* bn = g_norms[bnw];
    const bool mirror = (z < 2) && (bm != bc);
    const unsigned int hw = mirror ? 2u : 1u;   // hist weight (xx only)
    float* T = sm;  // transposed staging [128][129] — reuses As/Bs space

    if (mirror) __syncthreads();   // k-loop smem reads complete before overwrite

#pragma unroll
    for (int i = 0; i < 8; i++) {
        int rl = ty + 16 * i;
        int r  = bm + rl;
        float base2 = an[r];
#pragma unroll
        for (int h = 0; h < 4; h++) {
            int cl = 2 * tx + 32 * h;
            int c  = bc + cl;
            float2 o;
            o.x = fmaf(-2.0f, acc[i][2 * h + 0], base2 + bn[c + 0]);
            o.y = fmaf(-2.0f, acc[i][2 * h + 1], base2 + bn[c + 1]);
            *reinterpret_cast<float2*>(&OUT[(long long)r * NROW + c]) = o;
            if (mirror) {
                T[(cl + 0) * 129 + rl] = o.x;   // conflict-free: bank=2tx+ty(+1)
                T[(cl + 1) * 129 + rl] = o.y;
            }
            if (z == 0) {
                haddw(sh_hist, fkey(o.x) >> 21, hw);
                haddw(sh_hist, fkey(o.y) >> 21, hw);
            }
        }
    }

    if (mirror) {
        __syncthreads();
        int rr   = tid >> 1;
        int cb   = (tid & 1) * 64;
        long long obase = (long long)(bc + rr) * NROW + bm + cb;
#pragma unroll
        for (int v = 0; v < 16; v++) {
            float4 o;
            o.x = T[rr * 129 + cb + 4 * v + 0];
            o.y = T[rr * 129 + cb + 4 * v + 1];
            o.z = T[rr * 129 + cb + 4 * v + 2];
            o.w = T[rr * 129 + cb + 4 * v + 3];
            *reinterpret_cast<float4*>(&OUT[obase + 4 * v]) = o;
        }
    }

    if (z == 0) {
        __syncthreads();   // all hadds done
#pragma unroll
        for (int i = tid; i < 2048; i += 256) {
            unsigned int v = sh_hist[i];
            if (v) atomicAdd(&g_h0[i], v);
        }
    }
}

// ---- radix-select passes 1 & 2: full linear sweeps over g_xx ----
__global__ void k_hist1() {
    __shared__ unsigned int sh[2048];
    for (int i = threadIdx.x; i < 2048; i += 256) sh[i] = 0u;
    __syncthreads();
    const unsigned int pfx = g_pfx0;
    const float4* p = reinterpret_cast<const float4*>(g_xx);
    unsigned int i = blockIdx.x * 256u + threadIdx.x;
    const unsigned int stride = 1024u * 256u;
    for (int it = 0; it < 16; it++, i += stride) {
        float4 v = p[i];
        unsigned int k;
        k = fkey(v.x); if ((k >> 21) == pfx) atomicAdd(&sh[(k >> 10) & 2047u], 1u);
        k = fkey(v.y); if ((k >> 21) == pfx) atomicAdd(&sh[(k >> 10) & 2047u], 1u);
        k = fkey(v.z); if ((k >> 21) == pfx) atomicAdd(&sh[(k >> 10) & 2047u], 1u);
        k = fkey(v.w); if ((k >> 21) == pfx) atomicAdd(&sh[(k >> 10) & 2047u], 1u);
    }
    __syncthreads();
    for (int i2 = threadIdx.x; i2 < 2048; i2 += 256) {
        unsigned int v = sh[i2];
        if (v) atomicAdd(&g_h1[i2], v);
    }
}

__global__ void k_hist2() {
    __shared__ unsigned int sh[1024];
    for (int i = threadIdx.x; i < 1024; i += 256) sh[i] = 0u;
    __syncthreads();
    const unsigned int pfx = g_pfx1;
    const float4* p = reinterpret_cast<const float4*>(g_xx);
    unsigned int i = blockIdx.x * 256u + threadIdx.x;
    const unsigned int stride = 1024u * 256u;
    for (int it = 0; it < 16; it++, i += stride) {
        float4 v = p[i];
        unsigned int k;
        k = fkey(v.x); if ((k >> 10) == pfx) atomicAdd(&sh[k & 1023u], 1u);
        k = fkey(v.y); if ((k >> 10) == pfx) atomicAdd(&sh[k & 1023u], 1u);
        k = fkey(v.z); if ((k >> 10) == pfx) atomicAdd(&sh[k & 1023u], 1u);
        k = fkey(v.w); if ((k >> 10) == pfx) atomicAdd(&sh[k & 1023u], 1u);
    }
    __syncthreads();
    for (int i2 = threadIdx.x; i2 < 1024; i2 += 256) {
        unsigned int v = sh[i2];
        if (v) atomicAdd(&g_h2[i2], v);
    }
}

// Parallel radix-select step: per-thread segment sums, Hillis-Steele prefix
// across 64 threads, unique owner thread scans its <=32-bin segment.
__global__ void k_select(int pass, const float* __restrict__ ks) {
    __shared__ unsigned int sh[2048];
    __shared__ unsigned int ps[64];
    const unsigned int* hist = (pass == 0) ? g_h0 : (pass == 1) ? g_h1 : g_h2;
    const int nbins = (pass == 2) ? 1024 : 2048;
    const int per   = nbins / 64;
    const int tid   = threadIdx.x;  // 64 threads
    unsigned int s = 0;
    for (int i = 0; i < per; i++) {
        unsigned int v = hist[tid * per + i];
        sh[tid * per + i] = v;
        s += v;
    }
    ps[tid] = s;
    __syncthreads();
    // inclusive prefix over 64 entries
#pragma unroll
    for (int o = 1; o < 64; o <<= 1) {
        unsigned int v = ps[tid] + ((tid >= o) ? ps[tid - o] : 0u);
        __syncthreads();
        ps[tid] = v;
        __syncthreads();
    }
    const unsigned int rank = g_rank;
    const unsigned int incl = ps[tid];
    const unsigned int excl = incl - s;
    if (excl <= rank && rank < incl) {      // unique owner segment
        unsigned int cum = excl;
        int b = tid * per;
        while (cum + sh[b] <= rank) { cum += sh[b]; b++; }
        g_rank = rank - cum;
        if (pass == 0) {
            g_pfx0 = (unsigned int)b;
        } else if (pass == 1) {
            g_pfx1 = (g_pfx0 << 11) | (unsigned int)b;
        } else {
            unsigned int key  = (g_pfx1 << 10) | (unsigned int)b;
            unsigned int bits = (key & 0x80000000u) ? (key ^ 0x80000000u) : ~key;
            float med  = __uint_as_float(bits);
            float base = -1.0f / med;
            float p0 = base * ks[0], p1 = base * ks[1], p2 = base * ks[2];
            float p3 = base * ks[3], p4 = base * ks[4];
            g_par[0] = p0; g_par[1] = p1; g_par[2] = p2; g_par[3] = p3; g_par[4] = p4;
            bool fast = (p1 == 2.0f * p0) && (p2 == 2.0f * p1) &&
                        (p3 == 2.0f * p2) && (p4 == 2.0f * p3);
            g_par[5] = fast ? 1.0f : 0.0f;
        }
    }
}

// Stage-A XLA row-reduction replica (bit-exact per-row shape). TWO rows per
// block for doubled exp-chain ILP: rows 2*bx and 2*bx+1. grid=(2048, 3).
// Warp 0 reduces row 0, warp 1 reduces row 1 — identical 0-padded trees.
__global__ void __launch_bounds__(256) k_rowreduce() {
    __shared__ float ws0[8];
    __shared__ float ws1[8];
    const int r0   = blockIdx.x * 2;
    const int r1   = r0 + 1;
    const int slot = blockIdx.y;
    const int diagskip = (slot != 2) ? 1 : 0;
    const int t = threadIdx.x;
    float s0 = g_par[0], s1 = g_par[1], s2 = g_par[2], s3 = g_par[3], s4 = g_par[4];
    const bool fast = g_par[5] > 0.5f;
    const float* M = mat_of(slot);
    const float2* p0 = reinterpret_cast<const float2*>(M + (long long)r0 * NROW);
    const float2* p1 = reinterpret_cast<const float2*>(M + (long long)r1 * NROW);

    float ax0 = 0.0f, ay0 = 0.0f, ax1 = 0.0f, ay1 = 0.0f;
    if (fast) {
#pragma unroll
        for (int i = 0; i < 8; i++) {
            float2 v0 = p0[i * 256 + t];
            float2 v1 = p1[i * 256 + t];
            int c = (i * 256 + t) * 2;
            float kx0 = kmean5f(v0.x, s0);
            float ky0 = kmean5f(v0.y, s0);
            float kx1 = kmean5f(v1.x, s0);
            float ky1 = kmean5f(v1.y, s0);
            if (diagskip && c == r0)     kx0 = 0.0f;
            if (diagskip && c + 1 == r0) ky0 = 0.0f;
            if (diagskip && c == r1)     kx1 = 0.0f;
            if (diagskip && c + 1 == r1) ky1 = 0.0f;
            ax0 += kx0; ay0 += ky0;
            ax1 += kx1; ay1 += ky1;
        }
    } else {
#pragma unroll
        for (int i = 0; i < 8; i++) {
            float2 v0 = p0[i * 256 + t];
            float2 v1 = p1[i * 256 + t];
            int c = (i * 256 + t) * 2;
            float kx0 = kmean5(v0.x, s0, s1, s2, s3, s4);
            float ky0 = kmean5(v0.y, s0, s1, s2, s3, s4);
            float kx1 = kmean5(v1.x, s0, s1, s2, s3, s4);
            float ky1 = kmean5(v1.y, s0, s1, s2, s3, s4);
            if (diagskip && c == r0)     kx0 = 0.0f;
            if (diagskip && c + 1 == r0) ky0 = 0.0f;
            if (diagskip && c == r1)     kx1 = 0.0f;
            if (diagskip && c + 1 == r1) ky1 = 0.0f;
            ax0 += kx0; ay0 += ky0;
            ax1 += kx1; ay1 += ky1;
        }
    }
    float v0 = ax0 + ay0;
    float v1 = ax1 + ay1;
#pragma unroll
    for (int o = 16; o > 0; o >>= 1) {
        v0 += __shfl_down_sync(0xffffffffu, v0, o);
        v1 += __shfl_down_sync(0xffffffffu, v1, o);
    }
    if ((t & 31) == 0) { ws0[t >> 5] = v0; ws1[t >> 5] = v1; }
    __syncthreads();
    if (t < 32) {
        float w = (t < 8) ? ws0[t] : 0.0f;
#pragma unroll
        for (int o = 16; o > 0; o >>= 1) w += __shfl_down_sync(0xffffffffu, w, o);
        if (t == 0) g_rows[slot][r0] = w;
    } else if (t < 64) {
        int l = t - 32;
        float w = (l < 8) ? ws1[l] : 0.0f;
#pragma unroll
        for (int o = 16; o > 0; o >>= 1) w += __shfl_down_sync(0xffffffffu, w, o);
        if (l == 0) g_rows[slot][r1] = w;
    }
}

// Stage-B + fused final combine: same reduce shape over the 4096 f32 row
// sums; the LAST completing block performs the final f32 combine.
__global__ void __launch_bounds__(256) k_stageB(float* out) {
    __shared__ float ws[8];
    const int slot = blockIdx.x;
    const int t = threadIdx.x;
    const float2* p = reinterpret_cast<const float2*>(g_rows[slot]);
    float ax = 0.0f, ay = 0.0f;
#pragma unroll
    for (int i = 0; i < 8; i++) {
        float2 v = p[i * 256 + t];
        ax += v.x;
        ay += v.y;
    }
    float v = ax + ay;
#pragma unroll
    for (int o = 16; o > 0; o >>= 1) v += __shfl_down_sync(0xffffffffu, v, o);
    if ((t & 31) == 0) ws[t >> 5] = v;
    __syncthreads();
    if (t == 0) {
        float w = 0.0f;   // warp-equivalent: serial sum of 8 partials is fine
        // replicate the 0-padded warp tree exactly: tree over [ws0..ws7,0...]
        // is equal to left-to-right pairwise tree; use the same shfl tree:
    }
    if (t < 32) {
        float w = (t < 8) ? ws[t] : 0.0f;
#pragma unroll
        for (int o = 16; o > 0; o >>= 1) w += __shfl_down_sync(0xffffffffu, w, o);
        if (t == 0) {
            g_S[slot] = w;
            __threadfence();
            unsigned int d = atomicAdd(&g_done, 1u);
            if (d == 2u) {   // last of 3 blocks: do the final combine
                float S1 = g_S[0], S2 = g_S[1], S3 = g_S[2];
                float od = (float)(1.0 / 16773120.0);   // 1/(4096*4095) f32
                float t1 = od * S1;
                float t2 = od * S2;
                float m3 = S3 * (1.0f / 16777216.0f);   // exact pow2 scale
                float t3 = 2.0f * m3;                   // exact
                out[0] = (t1 + t2) - t3;
            }
        }
    }
}

// ---------------- entry ----------------
extern "C" void kernel_launch(void* const* d_in, const int* in_sizes, int n_in,
                              void* d_out, int out_size) {
    (void)in_sizes; (void)n_in; (void)out_size;
    const float* x  = (const float*)d_in[0];
    const float* y  = (const float*)d_in[1];
    const float* ks = (const float*)d_in[2];

    const int TILE_SMEM = 2 * 128 * 69 * (int)sizeof(float);  // 70656 B dynamic
    cudaFuncSetAttribute(k_tile128, cudaFuncAttributeMaxDynamicSharedMemorySize,
                         TILE_SMEM);

    k_init<<<1, 256>>>();
    dim3 rn(512, 2);
    k_rownorm<<<rn, 256>>>(x, y);

    // 528 (xx tri, +fused hist0) + 528 (yy tri) + 1024 (zz full) = 2080 blocks
    k_tile128<<<2080, 256, TILE_SMEM>>>(x, y);

    k_select<<<1, 64>>>(0, ks);          // pass-0 select (hist fused in tiles)
    k_hist1<<<1024, 256>>>();
    k_select<<<1, 64>>>(1, ks);
    k_hist2<<<1024, 256>>>();
    k_select<<<1, 64>>>(2, ks);          // -> median, scales, fast flag

    dim3 rg(2048, 3);
    k_rowreduce<<<rg, 256>>>();          // stage-A rows (2 rows/block)
    k_stageB<<<3, 256>>>((float*)d_out); // stage-B sums + fused final combine
}

// round 15
// speedup vs baseline: 2.1621x; 1.0024x over previous
#include <cuda_runtime.h>
#include <math.h>

#define NROW 4096
#define DDIM 64

// ---------------- device scratch (no allocations allowed) ----------------
static __device__ float        g_xx[(long long)NROW * NROW];   // 64 MB dist(x,x)
static __device__ float        g_yy[(long long)NROW * NROW];   // 64 MB dist(y,y)
static __device__ float        g_zz[(long long)NROW * NROW];   // 64 MB dist(x,y)
static __device__ float        g_norms[2][NROW];               // row norms of x, y
static __device__ float        g_rows[3][NROW];                // stage-A f32 row sums
static __device__ float        g_S[3];                         // stage-B f32 sums
static __device__ unsigned int g_h0[2048];
static __device__ unsigned int g_h1[2048];
static __device__ unsigned int g_h2[1024];
static __device__ unsigned int g_pfx0, g_pfx1, g_rank;
static __device__ unsigned int g_cnt[4];   // completion counters (tile, h1, h2, stageB)
static __device__ float        g_par[8];   // [0..4]=s_k, [5]=fast-chain flag

// device-side selector (never pass __device__ symbols from host code)
__device__ __forceinline__ float* mat_of(int slot) {
    return (slot == 0) ? g_xx : (slot == 1) ? g_yy : g_zz;
}

// ---------------- helpers ----------------
// Cephes-style minimax expf (~1 ulp). Proven: rel_err == 0.0 end-to-end.
__device__ __forceinline__ float my_exp(float x) {
    x = fmaxf(x, -87.0f);
    float z = floorf(fmaf(x, 1.44269504088896341f, 0.5f));
    float r = fmaf(z, -0.693359375f, x);
    r = fmaf(z, 2.12194440e-4f, r);
    int n = (int)z;
    float p = 1.9875691500e-4f;
    p = fmaf(p, r, 1.3981999507e-3f);
    p = fmaf(p, r, 8.3334519073e-3f);
    p = fmaf(p, r, 4.1665795894e-2f);
    p = fmaf(p, r, 1.6666665459e-1f);
    p = fmaf(p, r, 5.0000001201e-1f);
    float res = fmaf(p, r * r, r) + 1.0f;
    return res * __int_as_float((n + 127) << 23);
}

// exact-replica 5-exp kernel mean: ((((e0+e1)+e2)+e3)+e4) / 5.0f
__device__ __forceinline__ float kmean5(float d, float s0, float s1, float s2,
                                        float s3, float s4) {
    float s = my_exp(d * s0);
    s = s + my_exp(d * s1);
    s = s + my_exp(d * s2);
    s = s + my_exp(d * s3);
    s = s + my_exp(d * s4);
    return s / 5.0f;
}

// fast chain (valid when s_{k+1} == 2*s_k exactly): 2 exps + 3 muls.
__device__ __forceinline__ float kmean5f(float d, float s0) {
    float v  = d * s0;
    float e0 = my_exp(v);
    float e2 = my_exp(4.0f * v);
    float e1 = e0 * e0;      // exp(2v)
    float e3 = e2 * e2;      // exp(8v)
    float e4 = e3 * e3;      // exp(16v)
    float s = e0 + e1;
    s = s + e2;
    s = s + e3;
    s = s + e4;
    return s / 5.0f;
}

// monotone key transform for float radix select
__device__ __forceinline__ unsigned int fkey(float f) {
    unsigned int b = __float_as_uint(f);
    return b ^ ((b & 0x80000000u) ? 0xffffffffu : 0x80000000u);
}

// warp-aggregated shared histogram add (weighted)
__device__ __forceinline__ void haddw(unsigned int* sh, unsigned int bin,
                                      unsigned int w) {
    unsigned int m = __match_any_sync(0xffffffffu, bin);
    if ((int)(threadIdx.x & 31u) == (int)(__ffs(m) - 1))
        atomicAdd(&sh[bin], (unsigned int)__popc(m) * w);
}

// In-kernel radix-select step, executed by ONE 256-thread block (the last
// finisher of the producing kernel). Integer-only.
__device__ void do_select(int pass, const float* __restrict__ ks) {
    __shared__ unsigned int sel_sh[2048];
    __shared__ unsigned int sel_ps[256];
    const unsigned int* hist = (pass == 0) ? g_h0 : (pass == 1) ? g_h1 : g_h2;
    const int nbins = (pass == 2) ? 1024 : 2048;
    const int per   = nbins / 256;          // 8 or 4
    const int tid   = threadIdx.x;
    unsigned int s = 0;
    for (int i = 0; i < per; i++) {
        unsigned int v = hist[tid * per + i];
        sel_sh[tid * per + i] = v;
        s += v;
    }
    sel_ps[tid] = s;
    __syncthreads();
#pragma unroll
    for (int o = 1; o < 256; o <<= 1) {
        unsigned int v = sel_ps[tid] + ((tid >= o) ? sel_ps[tid - o] : 0u);
        __syncthreads();
        sel_ps[tid] = v;
        __syncthreads();
    }
    const unsigned int rank = g_rank;
    const unsigned int incl = sel_ps[tid];
    const unsigned int excl = incl - s;
    if (excl <= rank && rank < incl) {      // unique owner thread
        unsigned int cum = excl;
        int b = tid * per;
        while (cum + sel_sh[b] <= rank) { cum += sel_sh[b]; b++; }
        g_rank = rank - cum;
        if (pass == 0) {
            g_pfx0 = (unsigned int)b;
        } else if (pass == 1) {
            g_pfx1 = (g_pfx0 << 11) | (unsigned int)b;
        } else {
            unsigned int key  = (g_pfx1 << 10) | (unsigned int)b;
            unsigned int bits = (key & 0x80000000u) ? (key ^ 0x80000000u) : ~key;
            float med  = __uint_as_float(bits);
            float base = -1.0f / med;
            float p0 = base * ks[0], p1 = base * ks[1], p2 = base * ks[2];
            float p3 = base * ks[3], p4 = base * ks[4];
            g_par[0] = p0; g_par[1] = p1; g_par[2] = p2; g_par[3] = p3; g_par[4] = p4;
            bool fast = (p1 == 2.0f * p0) && (p2 == 2.0f * p1) &&
                        (p3 == 2.0f * p2) && (p4 == 2.0f * p3);
            g_par[5] = fast ? 1.0f : 0.0f;
        }
    }
}

// last-block detector: returns true (uniformly across the block) for the
// final block of the grid to pass this point.
__device__ bool last_block(int which, unsigned int total) {
    __shared__ unsigned int isl;
    __threadfence();
    __syncthreads();
    if (threadIdx.x == 0)
        isl = (atomicAdd(&g_cnt[which], 1u) == total - 1u) ? 1u : 0u;
    __syncthreads();
    return isl != 0u;
}

// ---------------- kernels ----------------
// merged init + row norms: blockIdx.y selects x (0) or y (1)
__global__ void k_rownorm(const float* __restrict__ x, const float* __restrict__ y) {
    if (blockIdx.x == 0 && blockIdx.y == 0) {
        int t = threadIdx.x;
        for (int i = t; i < 2048; i += 256) { g_h0[i] = 0u; g_h1[i] = 0u; }
        for (int i = t; i < 1024; i += 256) g_h2[i] = 0u;
        if (t == 0) {
            g_rank = 8388607u;  // (N*N - 1) / 2 : lower-median rank
            g_pfx0 = 0u; g_pfx1 = 0u;
            g_cnt[0] = 0u; g_cnt[1] = 0u; g_cnt[2] = 0u; g_cnt[3] = 0u;
        }
    }
    int which = blockIdx.y;
    const float* a = which ? y : x;
    int row  = blockIdx.x * 8 + (threadIdx.x >> 5);
    int lane = threadIdx.x & 31;
    float v0 = a[row * DDIM + lane];
    float v1 = a[row * DDIM + 32 + lane];
    float s  = v0 * v0 + v1 * v1;
#pragma unroll
    for (int o = 16; o > 0; o >>= 1) s += __shfl_down_sync(0xffffffffu, s, o);
    if (lane == 0) g_norms[which][row] = s;
}

// 128x128 tile, 256 threads, 8x8/thread, K=64. Symmetry-aware, bit-exact
// mirror for xx/yy off-diagonal blocks. xx blocks build the pass-0 median
// histogram (weight 2 on mirrored) — integer-exact. The LAST block of the
// grid additionally runs select pass 0.
// Linear grid: [0,528)=xx tri, [528,1056)=yy tri, [1056,2080)=zz full.
__global__ void __launch_bounds__(256, 2) k_tile128(const float* __restrict__ x,
                                                    const float* __restrict__ y,
                                                    const float* __restrict__ ks) {
    extern __shared__ float sm[];
    float* As = sm;             // [128][69]
    float* Bs = sm + 128 * 69;  // [128][69]
    __shared__ unsigned int sh_hist[2048];

    int idx = blockIdx.x;
    int z, bxb, byb;
    if (idx < 1056) {
        z = (idx < 528) ? 0 : 1;
        int t = idx - z * 528;
        int by = (int)((sqrtf(8.0f * (float)t + 1.0f) - 1.0f) * 0.5f);
        while (by * (by + 1) / 2 > t) by--;
        while ((by + 1) * (by + 2) / 2 <= t) by++;
        byb = by;
        bxb = t - by * (by + 1) / 2;     // bxb <= byb
    } else {
        z = 2;
        int t = idx - 1056;
        bxb = t & 31;
        byb = t >> 5;
    }

    const float* A = (z == 1) ? y : x;
    const float* B = (z == 0) ? x : y;
    const int anw = (z == 1) ? 1 : 0;
    const int bnw = (z == 0) ? 0 : 1;
    float* OUT = mat_of(z);

    const int bm  = byb * 128;
    const int bc  = bxb * 128;
    const int tid = threadIdx.x;

    if (z == 0) {
#pragma unroll
        for (int i = tid; i < 2048; i += 256) sh_hist[i] = 0u;
    }

    const float4* Ag = reinterpret_cast<const float4*>(A + (long long)bm * DDIM);
    const float4* Bg = reinterpret_cast<const float4*>(B + (long long)bc * DDIM);
#pragma unroll
    for (int i = tid; i < 2048; i += 256) {
        int row = i >> 4, f4 = i & 15;
        float4 va = Ag[row * 16 + f4];
        float4 vb = Bg[row * 16 + f4];
        int c4 = f4 * 4;
        As[row * 69 + c4 + 0] = va.x; As[row * 69 + c4 + 1] = va.y;
        As[row * 69 + c4 + 2] = va.z; As[row * 69 + c4 + 3] = va.w;
        Bs[row * 69 + c4 + 0] = vb.x; Bs[row * 69 + c4 + 1] = vb.y;
        Bs[row * 69 + c4 + 2] = vb.z; Bs[row * 69 + c4 + 3] = vb.w;
    }
    __syncthreads();

    const int tx = tid & 15, ty = tid >> 4;

    int arow[8], brow[8];
#pragma unroll
    for (int i = 0; i < 8; i++) arow[i] = (ty + 16 * i) * 69;
#pragma unroll
    for (int j = 0; j < 8; j++)
        brow[j] = (2 * tx + 32 * (j >> 1) + (j & 1)) * 69;

    float acc[8][8];
#pragma unroll
    for (int i = 0; i < 8; i++)
#pragma unroll
        for (int j = 0; j < 8; j++) acc[i][j] = 0.0f;

    float a0[8], b0[8], a1[8], b1[8];
#pragma unroll
    for (int i = 0; i < 8; i++) a0[i] = As[arow[i]];
#pragma unroll
    for (int j = 0; j < 8; j++) b0[j] = Bs[brow[j]];

#pragma unroll 4
    for (int k = 0; k < 64; k += 2) {
#pragma unroll
        for (int i = 0; i < 8; i++) a1[i] = As[arow[i] + k + 1];
#pragma unroll
        for (int j = 0; j < 8; j++) b1[j] = Bs[brow[j] + k + 1];
#pragma unroll
        for (int i = 0; i < 8; i++)
#pragma unroll
            for (int j = 0; j < 8; j++)
                acc[i][j] = fmaf(a0[i], b0[j], acc[i][j]);
#pragma unroll
        for (int i = 0; i < 8; i++) a0[i] = As[arow[i] + k + 2];  // k=62 -> pad col
#pragma unroll
        for (int j = 0; j < 8; j++) b0[j] = Bs[brow[j] + k + 2];
#pragma unroll
        for (int i = 0; i < 8; i++)
#pragma unroll
            for (int j = 0; j < 8; j++)
                acc[i][j] = fmaf(a1[i], b1[j], acc[i][j]);
    }

    const float* an = g_norms[anw];
    const float* bn = g_norms[bnw];
    const bool mirror = (z < 2) && (bm != bc);
    const unsigned int hw = mirror ? 2u : 1u;   // hist weight (xx only)
    float* T = sm;  // transposed staging [128][129] — reuses As/Bs space

    if (mirror) __syncthreads();   // k-loop smem reads complete before overwrite

#pragma unroll
    for (int i = 0; i < 8; i++) {
        int rl = ty + 16 * i;
        int r  = bm + rl;
        float base2 = an[r];
#pragma unroll
        for (int h = 0; h < 4; h++) {
            int cl = 2 * tx + 32 * h;
            int c  = bc + cl;
            float2 o;
            o.x = fmaf(-2.0f, acc[i][2 * h + 0], base2 + bn[c + 0]);
            o.y = fmaf(-2.0f, acc[i][2 * h + 1], base2 + bn[c + 1]);
            *reinterpret_cast<float2*>(&OUT[(long long)r * NROW + c]) = o;
            if (mirror) {
                T[(cl + 0) * 129 + rl] = o.x;   // conflict-free: bank=2tx+ty(+1)
                T[(cl + 1) * 129 + rl] = o.y;
            }
            if (z == 0) {
                haddw(sh_hist, fkey(o.x) >> 21, hw);
                haddw(sh_hist, fkey(o.y) >> 21, hw);
            }
        }
    }

    if (mirror) {
        __syncthreads();
        int rr   = tid >> 1;
        int cb   = (tid & 1) * 64;
        long long obase = (long long)(bc + rr) * NROW + bm + cb;
#pragma unroll
        for (int v = 0; v < 16; v++) {
            float4 o;
            o.x = T[rr * 129 + cb + 4 * v + 0];
            o.y = T[rr * 129 + cb + 4 * v + 1];
            o.z = T[rr * 129 + cb + 4 * v + 2];
            o.w = T[rr * 129 + cb + 4 * v + 3];
            *reinterpret_cast<float4*>(&OUT[obase + 4 * v]) = o;
        }
    }

    if (z == 0) {
        __syncthreads();   // all hadds done
#pragma unroll
        for (int i = tid; i < 2048; i += 256) {
            unsigned int v = sh_hist[i];
            if (v) atomicAdd(&g_h0[i], v);
        }
    }

    // last block of the whole grid runs select pass 0
    if (last_block(0, 2080u)) do_select(0, ks);
}

// ---- radix-select passes 1 & 2: full sweeps; last block runs the select ----
__global__ void k_hist1(const float* __restrict__ ks) {
    __shared__ unsigned int sh[2048];
    for (int i = threadIdx.x; i < 2048; i += 256) sh[i] = 0u;
    __syncthreads();
    const unsigned int pfx = g_pfx0;
    const float4* p = reinterpret_cast<const float4*>(g_xx);
    unsigned int i = blockIdx.x * 256u + threadIdx.x;
    const unsigned int stride = 1024u * 256u;
    for (int it = 0; it < 16; it++, i += stride) {
        float4 v = p[i];
        unsigned int k;
        k = fkey(v.x); if ((k >> 21) == pfx) atomicAdd(&sh[(k >> 10) & 2047u], 1u);
        k = fkey(v.y); if ((k >> 21) == pfx) atomicAdd(&sh[(k >> 10) & 2047u], 1u);
        k = fkey(v.z); if ((k >> 21) == pfx) atomicAdd(&sh[(k >> 10) & 2047u], 1u);
        k = fkey(v.w); if ((k >> 21) == pfx) atomicAdd(&sh[(k >> 10) & 2047u], 1u);
    }
    __syncthreads();
    for (int i2 = threadIdx.x; i2 < 2048; i2 += 256) {
        unsigned int v = sh[i2];
        if (v) atomicAdd(&g_h1[i2], v);
    }
    if (last_block(1, 1024u)) do_select(1, ks);
}

__global__ void k_hist2(const float* __restrict__ ks) {
    __shared__ unsigned int sh[1024];
    for (int i = threadIdx.x; i < 1024; i += 256) sh[i] = 0u;
    __syncthreads();
    const unsigned int pfx = g_pfx1;
    const float4* p = reinterpret_cast<const float4*>(g_xx);
    unsigned int i = blockIdx.x * 256u + threadIdx.x;
    const unsigned int stride = 1024u * 256u;
    for (int it = 0; it < 16; it++, i += stride) {
        float4 v = p[i];
        unsigned int k;
        k = fkey(v.x); if ((k >> 10) == pfx) atomicAdd(&sh[k & 1023u], 1u);
        k = fkey(v.y); if ((k >> 10) == pfx) atomicAdd(&sh[k & 1023u], 1u);
        k = fkey(v.z); if ((k >> 10) == pfx) atomicAdd(&sh[k & 1023u], 1u);
        k = fkey(v.w); if ((k >> 10) == pfx) atomicAdd(&sh[k & 1023u], 1u);
    }
    __syncthreads();
    for (int i2 = threadIdx.x; i2 < 1024; i2 += 256) {
        unsigned int v = sh[i2];
        if (v) atomicAdd(&g_h2[i2], v);
    }
    if (last_block(2, 1024u)) do_select(2, ks);
}

// Stage-A XLA row-reduction replica (bit-exact per-row shape). TWO rows per
// block: rows 2*bx, 2*bx+1. grid=(2048, 3).
__global__ void __launch_bounds__(256) k_rowreduce() {
    __shared__ float ws0[8];
    __shared__ float ws1[8];
    const int r0   = blockIdx.x * 2;
    const int r1   = r0 + 1;
    const int slot = blockIdx.y;
    const int diagskip = (slot != 2) ? 1 : 0;
    const int t = threadIdx.x;
    float s0 = g_par[0], s1 = g_par[1], s2 = g_par[2], s3 = g_par[3], s4 = g_par[4];
    const bool fast = g_par[5] > 0.5f;
    const float* M = mat_of(slot);
    const float2* p0 = reinterpret_cast<const float2*>(M + (long long)r0 * NROW);
    const float2* p1 = reinterpret_cast<const float2*>(M + (long long)r1 * NROW);

    float ax0 = 0.0f, ay0 = 0.0f, ax1 = 0.0f, ay1 = 0.0f;
    if (fast) {
#pragma unroll
        for (int i = 0; i < 8; i++) {
            float2 v0 = p0[i * 256 + t];
            float2 v1 = p1[i * 256 + t];
            int c = (i * 256 + t) * 2;
            float kx0 = kmean5f(v0.x, s0);
            float ky0 = kmean5f(v0.y, s0);
            float kx1 = kmean5f(v1.x, s0);
            float ky1 = kmean5f(v1.y, s0);
            if (diagskip && c == r0)     kx0 = 0.0f;
            if (diagskip && c + 1 == r0) ky0 = 0.0f;
            if (diagskip && c == r1)     kx1 = 0.0f;
            if (diagskip && c + 1 == r1) ky1 = 0.0f;
            ax0 += kx0; ay0 += ky0;
            ax1 += kx1; ay1 += ky1;
        }
    } else {
#pragma unroll
        for (int i = 0; i < 8; i++) {
            float2 v0 = p0[i * 256 + t];
            float2 v1 = p1[i * 256 + t];
            int c = (i * 256 + t) * 2;
            float kx0 = kmean5(v0.x, s0, s1, s2, s3, s4);
            float ky0 = kmean5(v0.y, s0, s1, s2, s3, s4);
            float kx1 = kmean5(v1.x, s0, s1, s2, s3, s4);
            float ky1 = kmean5(v1.y, s0, s1, s2, s3, s4);
            if (diagskip && c == r0)     kx0 = 0.0f;
            if (diagskip && c + 1 == r0) ky0 = 0.0f;
            if (diagskip && c == r1)     kx1 = 0.0f;
            if (diagskip && c + 1 == r1) ky1 = 0.0f;
            ax0 += kx0; ay0 += ky0;
            ax1 += kx1; ay1 += ky1;
        }
    }
    float v0 = ax0 + ay0;
    float v1 = ax1 + ay1;
#pragma unroll
    for (int o = 16; o > 0; o >>= 1) {
        v0 += __shfl_down_sync(0xffffffffu, v0, o);
        v1 += __shfl_down_sync(0xffffffffu, v1, o);
    }
    if ((t & 31) == 0) { ws0[t >> 5] = v0; ws1[t >> 5] = v1; }
    __syncthreads();
    if (t < 32) {
        float w = (t < 8) ? ws0[t] : 0.0f;
#pragma unroll
        for (int o = 16; o > 0; o >>= 1) w += __shfl_down_sync(0xffffffffu, w, o);
        if (t == 0) g_rows[slot][r0] = w;
    } else if (t < 64) {
        int l = t - 32;
        float w = (l < 8) ? ws1[l] : 0.0f;
#pragma unroll
        for (int o = 16; o > 0; o >>= 1) w += __shfl_down_sync(0xffffffffu, w, o);
        if (l == 0) g_rows[slot][r1] = w;
    }
}

// Stage-B + fused final combine: the last completing block does the combine.
__global__ void __launch_bounds__(256) k_stageB(float* out) {
    __shared__ float ws[8];
    const int slot = blockIdx.x;
    const int t = threadIdx.x;
    const float2* p = reinterpret_cast<const float2*>(g_rows[slot]);
    float ax = 0.0f, ay = 0.0f;
#pragma unroll
    for (int i = 0; i < 8; i++) {
        float2 v = p[i * 256 + t];
        ax += v.x;
        ay += v.y;
    }
    float v = ax + ay;
#pragma unroll
    for (int o = 16; o > 0; o >>= 1) v += __shfl_down_sync(0xffffffffu, v, o);
    if ((t & 31) == 0) ws[t >> 5] = v;
    __syncthreads();
    if (t < 32) {
        float w = (t < 8) ? ws[t] : 0.0f;
#pragma unroll
        for (int o = 16; o > 0; o >>= 1) w += __shfl_down_sync(0xffffffffu, w, o);
        if (t == 0) {
            g_S[slot] = w;
            __threadfence();
            unsigned int d = atomicAdd(&g_cnt[3], 1u);
            if (d == 2u) {   // last of 3 blocks: final combine
                float S1 = g_S[0], S2 = g_S[1], S3 = g_S[2];
                float od = (float)(1.0 / 16773120.0);   // 1/(4096*4095) f32
                float t1 = od * S1;
                float t2 = od * S2;
                float m3 = S3 * (1.0f / 16777216.0f);   // exact pow2 scale
                float t3 = 2.0f * m3;                   // exact
                out[0] = (t1 + t2) - t3;
            }
        }
    }
}

// ---------------- entry ----------------
extern "C" void kernel_launch(void* const* d_in, const int* in_sizes, int n_in,
                              void* d_out, int out_size) {
    (void)in_sizes; (void)n_in; (void)out_size;
    const float* x  = (const float*)d_in[0];
    const float* y  = (const float*)d_in[1];
    const float* ks = (const float*)d_in[2];

    const int TILE_SMEM = 2 * 128 * 69 * (int)sizeof(float);  // 70656 B dynamic
    cudaFuncSetAttribute(k_tile128, cudaFuncAttributeMaxDynamicSharedMemorySize,
                         TILE_SMEM);

    dim3 rn(512, 2);
    k_rownorm<<<rn, 256>>>(x, y);                 // init + row norms

    // 528 (xx tri, +hist0, +select0 in last block) + 528 (yy) + 1024 (zz)
    k_tile128<<<2080, 256, TILE_SMEM>>>(x, y, ks);

    k_hist1<<<1024, 256>>>(ks);                   // + select1 in last block
    k_hist2<<<1024, 256>>>(ks);                   // + select2 in last block

    dim3 rg(2048, 3);
    k_rowreduce<<<rg, 256>>>();                   // stage-A rows (2 rows/block)
    k_stageB<<<3, 256>>>((float*)d_out);          // stage-B + final combine
}

// round 16
// speedup vs baseline: 2.2609x; 1.0457x over previous
#include <cuda_runtime.h>
#include <math.h>

#define NROW 4096
#define DDIM 64

// ---------------- device scratch (no allocations allowed) ----------------
static __device__ float        g_xx[(long long)NROW * NROW];   // 64 MB dist(x,x)
static __device__ float        g_yy[(long long)NROW * NROW];   // 64 MB dist(y,y)
static __device__ float        g_zz[(long long)NROW * NROW];   // 64 MB dist(x,y)
static __device__ float        g_norms[2][NROW];               // row norms of x, y
static __device__ float        g_rows[3][NROW];                // stage-A f32 row sums
static __device__ float        g_S[3];                         // stage-B f32 sums
static __device__ unsigned int g_h0[2048];
static __device__ unsigned int g_h1[2048];
static __device__ unsigned int g_h2[1024];
static __device__ unsigned int g_pfx0, g_pfx1, g_rank;
static __device__ unsigned int g_cnt[4];   // completion counters (tile, h1, h2, stageB)
static __device__ float        g_par[8];   // [0..4]=s_k, [5]=fast-chain flag

// device-side selector (never pass __device__ symbols from host code)
__device__ __forceinline__ float* mat_of(int slot) {
    return (slot == 0) ? g_xx : (slot == 1) ? g_yy : g_zz;
}

// ---------------- helpers ----------------
// Cephes-style minimax expf (~1 ulp). Proven: rel_err == 0.0 end-to-end.
__device__ __forceinline__ float my_exp(float x) {
    x = fmaxf(x, -87.0f);
    float z = floorf(fmaf(x, 1.44269504088896341f, 0.5f));
    float r = fmaf(z, -0.693359375f, x);
    r = fmaf(z, 2.12194440e-4f, r);
    int n = (int)z;
    float p = 1.9875691500e-4f;
    p = fmaf(p, r, 1.3981999507e-3f);
    p = fmaf(p, r, 8.3334519073e-3f);
    p = fmaf(p, r, 4.1665795894e-2f);
    p = fmaf(p, r, 1.6666665459e-1f);
    p = fmaf(p, r, 5.0000001201e-1f);
    float res = fmaf(p, r * r, r) + 1.0f;
    return res * __int_as_float((n + 127) << 23);
}

// Markstein correctly-rounded-constant-division by 5: 3 FMA-class ops instead
// of a full IEEE div sequence. Bias-free (unlike bare *0.2f, whose +1.5e-8
// relative bias would coherently shift the S sums by ~0.055 and risk flipping
// an f32 rounding bin). Rare misroundings are sparse zero-mean ±1ulp noise.
__device__ __forceinline__ float div5(float s) {
    float q0 = s * 0.2f;
    float e  = fmaf(-5.0f, q0, s);
    return fmaf(e, 0.2f, q0);
}

// exact-replica 5-exp kernel mean: ((((e0+e1)+e2)+e3)+e4) / 5
__device__ __forceinline__ float kmean5(float d, float s0, float s1, float s2,
                                        float s3, float s4) {
    float s = my_exp(d * s0);
    s = s + my_exp(d * s1);
    s = s + my_exp(d * s2);
    s = s + my_exp(d * s3);
    s = s + my_exp(d * s4);
    return div5(s);
}

// fast chain (valid when s_{k+1} == 2*s_k exactly): 2 exps + 3 muls.
__device__ __forceinline__ float kmean5f(float d, float s0) {
    float v  = d * s0;
    float e0 = my_exp(v);
    float e2 = my_exp(4.0f * v);
    float e1 = e0 * e0;      // exp(2v)
    float e3 = e2 * e2;      // exp(8v)
    float e4 = e3 * e3;      // exp(16v)
    float s = e0 + e1;
    s = s + e2;
    s = s + e3;
    s = s + e4;
    return div5(s);
}

// monotone key transform for float radix select
__device__ __forceinline__ unsigned int fkey(float f) {
    unsigned int b = __float_as_uint(f);
    return b ^ ((b & 0x80000000u) ? 0xffffffffu : 0x80000000u);
}

// warp-aggregated shared histogram add (weighted)
__device__ __forceinline__ void haddw(unsigned int* sh, unsigned int bin,
                                      unsigned int w) {
    unsigned int m = __match_any_sync(0xffffffffu, bin);
    if ((int)(threadIdx.x & 31u) == (int)(__ffs(m) - 1))
        atomicAdd(&sh[bin], (unsigned int)__popc(m) * w);
}

// In-kernel radix-select step, executed by ONE 256-thread block (the last
// finisher of the producing kernel). Integer-only.
__device__ void do_select(int pass, const float* __restrict__ ks) {
    __shared__ unsigned int sel_sh[2048];
    __shared__ unsigned int sel_ps[256];
    const unsigned int* hist = (pass == 0) ? g_h0 : (pass == 1) ? g_h1 : g_h2;
    const int nbins = (pass == 2) ? 1024 : 2048;
    const int per   = nbins / 256;          // 8 or 4
    const int tid   = threadIdx.x;
    unsigned int s = 0;
    for (int i = 0; i < per; i++) {
        unsigned int v = hist[tid * per + i];
        sel_sh[tid * per + i] = v;
        s += v;
    }
    sel_ps[tid] = s;
    __syncthreads();
#pragma unroll
    for (int o = 1; o < 256; o <<= 1) {
        unsigned int v = sel_ps[tid] + ((tid >= o) ? sel_ps[tid - o] : 0u);
        __syncthreads();
        sel_ps[tid] = v;
        __syncthreads();
    }
    const unsigned int rank = g_rank;
    const unsigned int incl = sel_ps[tid];
    const unsigned int excl = incl - s;
    if (excl <= rank && rank < incl) {      // unique owner thread
        unsigned int cum = excl;
        int b = tid * per;
        while (cum + sel_sh[b] <= rank) { cum += sel_sh[b]; b++; }
        g_rank = rank - cum;
        if (pass == 0) {
            g_pfx0 = (unsigned int)b;
        } else if (pass == 1) {
            g_pfx1 = (g_pfx0 << 11) | (unsigned int)b;
        } else {
            unsigned int key  = (g_pfx1 << 10) | (unsigned int)b;
            unsigned int bits = (key & 0x80000000u) ? (key ^ 0x80000000u) : ~key;
            float med  = __uint_as_float(bits);
            float base = -1.0f / med;
            float p0 = base * ks[0], p1 = base * ks[1], p2 = base * ks[2];
            float p3 = base * ks[3], p4 = base * ks[4];
            g_par[0] = p0; g_par[1] = p1; g_par[2] = p2; g_par[3] = p3; g_par[4] = p4;
            bool fast = (p1 == 2.0f * p0) && (p2 == 2.0f * p1) &&
                        (p3 == 2.0f * p2) && (p4 == 2.0f * p3);
            g_par[5] = fast ? 1.0f : 0.0f;
        }
    }
}

// last-block detector: returns true (uniformly across the block) for the
// final block of the grid to pass this point.
__device__ bool last_block(int which, unsigned int total) {
    __shared__ unsigned int isl;
    __threadfence();
    __syncthreads();
    if (threadIdx.x == 0)
        isl = (atomicAdd(&g_cnt[which], 1u) == total - 1u) ? 1u : 0u;
    __syncthreads();
    return isl != 0u;
}

// ---------------- kernels ----------------
// merged init + row norms: blockIdx.y selects x (0) or y (1)
__global__ void k_rownorm(const float* __restrict__ x, const float* __restrict__ y) {
    if (blockIdx.x == 0 && blockIdx.y == 0) {
        int t = threadIdx.x;
        for (int i = t; i < 2048; i += 256) { g_h0[i] = 0u; g_h1[i] = 0u; }
        for (int i = t; i < 1024; i += 256) g_h2[i] = 0u;
        if (t == 0) {
            g_rank = 8388607u;  // (N*N - 1) / 2 : lower-median rank
            g_pfx0 = 0u; g_pfx1 = 0u;
            g_cnt[0] = 0u; g_cnt[1] = 0u; g_cnt[2] = 0u; g_cnt[3] = 0u;
        }
    }
    int which = blockIdx.y;
    const float* a = which ? y : x;
    int row  = blockIdx.x * 8 + (threadIdx.x >> 5);
    int lane = threadIdx.x & 31;
    float v0 = a[row * DDIM + lane];
    float v1 = a[row * DDIM + 32 + lane];
    float s  = v0 * v0 + v1 * v1;
#pragma unroll
    for (int o = 16; o > 0; o >>= 1) s += __shfl_down_sync(0xffffffffu, s, o);
    if (lane == 0) g_norms[which][row] = s;
}

// 128x128 tile, 256 threads, 8x8/thread, K=64. Symmetry-aware, bit-exact
// mirror for xx/yy off-diagonal blocks. xx blocks build the pass-0 median
// histogram (weight 2 on mirrored) — integer-exact. The LAST block of the
// grid additionally runs select pass 0.
// Linear grid: [0,528)=xx tri, [528,1056)=yy tri, [1056,2080)=zz full.
__global__ void __launch_bounds__(256, 2) k_tile128(const float* __restrict__ x,
                                                    const float* __restrict__ y,
                                                    const float* __restrict__ ks) {
    extern __shared__ float sm[];
    float* As = sm;             // [128][69]
    float* Bs = sm + 128 * 69;  // [128][69]
    __shared__ unsigned int sh_hist[2048];

    int idx = blockIdx.x;
    int z, bxb, byb;
    if (idx < 1056) {
        z = (idx < 528) ? 0 : 1;
        int t = idx - z * 528;
        int by = (int)((sqrtf(8.0f * (float)t + 1.0f) - 1.0f) * 0.5f);
        while (by * (by + 1) / 2 > t) by--;
        while ((by + 1) * (by + 2) / 2 <= t) by++;
        byb = by;
        bxb = t - by * (by + 1) / 2;     // bxb <= byb
    } else {
        z = 2;
        int t = idx - 1056;
        bxb = t & 31;
        byb = t >> 5;
    }

    const float* A = (z == 1) ? y : x;
    const float* B = (z == 0) ? x : y;
    const int anw = (z == 1) ? 1 : 0;
    const int bnw = (z == 0) ? 0 : 1;
    float* OUT = mat_of(z);

    const int bm  = byb * 128;
    const int bc  = bxb * 128;
    const int tid = threadIdx.x;

    if (z == 0) {
#pragma unroll
        for (int i = tid; i < 2048; i += 256) sh_hist[i] = 0u;
    }

    const float4* Ag = reinterpret_cast<const float4*>(A + (long long)bm * DDIM);
    const float4* Bg = reinterpret_cast<const float4*>(B + (long long)bc * DDIM);
#pragma unroll
    for (int i = tid; i < 2048; i += 256) {
        int row = i >> 4, f4 = i & 15;
        float4 va = Ag[row * 16 + f4];
        float4 vb = Bg[row * 16 + f4];
        int c4 = f4 * 4;
        As[row * 69 + c4 + 0] = va.x; As[row * 69 + c4 + 1] = va.y;
        As[row * 69 + c4 + 2] = va.z; As[row * 69 + c4 + 3] = va.w;
        Bs[row * 69 + c4 + 0] = vb.x; Bs[row * 69 + c4 + 1] = vb.y;
        Bs[row * 69 + c4 + 2] = vb.z; Bs[row * 69 + c4 + 3] = vb.w;
    }
    __syncthreads();

    const int tx = tid & 15, ty = tid >> 4;

    int arow[8], brow[8];
#pragma unroll
    for (int i = 0; i < 8; i++) arow[i] = (ty + 16 * i) * 69;
#pragma unroll
    for (int j = 0; j < 8; j++)
        brow[j] = (2 * tx + 32 * (j >> 1) + (j & 1)) * 69;

    float acc[8][8];
#pragma unroll
    for (int i = 0; i < 8; i++)
#pragma unroll
        for (int j = 0; j < 8; j++) acc[i][j] = 0.0f;

    float a0[8], b0[8], a1[8], b1[8];
#pragma unroll
    for (int i = 0; i < 8; i++) a0[i] = As[arow[i]];
#pragma unroll
    for (int j = 0; j < 8; j++) b0[j] = Bs[brow[j]];

#pragma unroll 4
    for (int k = 0; k < 64; k += 2) {
#pragma unroll
        for (int i = 0; i < 8; i++) a1[i] = As[arow[i] + k + 1];
#pragma unroll
        for (int j = 0; j < 8; j++) b1[j] = Bs[brow[j] + k + 1];
#pragma unroll
        for (int i = 0; i < 8; i++)
#pragma unroll
            for (int j = 0; j < 8; j++)
                acc[i][j] = fmaf(a0[i], b0[j], acc[i][j]);
#pragma unroll
        for (int i = 0; i < 8; i++) a0[i] = As[arow[i] + k + 2];  // k=62 -> pad col
#pragma unroll
        for (int j = 0; j < 8; j++) b0[j] = Bs[brow[j] + k + 2];
#pragma unroll
        for (int i = 0; i < 8; i++)
#pragma unroll
            for (int j = 0; j < 8; j++)
                acc[i][j] = fmaf(a1[i], b1[j], acc[i][j]);
    }

    const float* an = g_norms[anw];
    const float* bn = g_norms[bnw];
    const bool mirror = (z < 2) && (bm != bc);
    const unsigned int hw = mirror ? 2u : 1u;   // hist weight (xx only)
    float* T = sm;  // transposed staging [128][129] — reuses As/Bs space

    if (mirror) __syncthreads();   // k-loop smem reads complete before overwrite

#pragma unroll
    for (int i = 0; i < 8; i++) {
        int rl = ty + 16 * i;
        int r  = bm + rl;
        float base2 = an[r];
#pragma unroll
        for (int h = 0; h < 4; h++) {
            int cl = 2 * tx + 32 * h;
            int c  = bc + cl;
            float2 o;
            o.x = fmaf(-2.0f, acc[i][2 * h + 0], base2 + bn[c + 0]);
            o.y = fmaf(-2.0f, acc[i][2 * h + 1], base2 + bn[c + 1]);
            *reinterpret_cast<float2*>(&OUT[(long long)r * NROW + c]) = o;
            if (mirror) {
                T[(cl + 0) * 129 + rl] = o.x;   // conflict-free: bank=2tx+ty(+1)
                T[(cl + 1) * 129 + rl] = o.y;
            }
            if (z == 0) {
                haddw(sh_hist, fkey(o.x) >> 21, hw);
                haddw(sh_hist, fkey(o.y) >> 21, hw);
            }
        }
    }

    if (mirror) {
        __syncthreads();
        int rr   = tid >> 1;
        int cb   = (tid & 1) * 64;
        long long obase = (long long)(bc + rr) * NROW + bm + cb;
#pragma unroll
        for (int v = 0; v < 16; v++) {
            float4 o;
            o.x = T[rr * 129 + cb + 4 * v + 0];
            o.y = T[rr * 129 + cb + 4 * v + 1];
            o.z = T[rr * 129 + cb + 4 * v + 2];
            o.w = T[rr * 129 + cb + 4 * v + 3];
            *reinterpret_cast<float4*>(&OUT[obase + 4 * v]) = o;
        }
    }

    if (z == 0) {
        __syncthreads();   // all hadds done
#pragma unroll
        for (int i = tid; i < 2048; i += 256) {
            unsigned int v = sh_hist[i];
            if (v) atomicAdd(&g_h0[i], v);
        }
    }

    // last block of the whole grid runs select pass 0
    if (last_block(0, 2080u)) do_select(0, ks);
}

// ---- radix-select passes 1 & 2: MLP-2 sweeps; last block runs the select ----
__global__ void k_hist1(const float* __restrict__ ks) {
    __shared__ unsigned int sh[2048];
    for (int i = threadIdx.x; i < 2048; i += 256) sh[i] = 0u;
    __syncthreads();
    const unsigned int pfx = g_pfx0;
    const float4* p = reinterpret_cast<const float4*>(g_xx);
    unsigned int i = blockIdx.x * 256u + threadIdx.x;
    const unsigned int stride = 1024u * 256u;
    for (int it = 0; it < 8; it++, i += 2u * stride) {
        float4 va = p[i];
        float4 vb = p[i + stride];        // both loads in flight (MLP=2)
        unsigned int k;
        k = fkey(va.x); if ((k >> 21) == pfx) atomicAdd(&sh[(k >> 10) & 2047u], 1u);
        k = fkey(va.y); if ((k >> 21) == pfx) atomicAdd(&sh[(k >> 10) & 2047u], 1u);
        k = fkey(va.z); if ((k >> 21) == pfx) atomicAdd(&sh[(k >> 10) & 2047u], 1u);
        k = fkey(va.w); if ((k >> 21) == pfx) atomicAdd(&sh[(k >> 10) & 2047u], 1u);
        k = fkey(vb.x); if ((k >> 21) == pfx) atomicAdd(&sh[(k >> 10) & 2047u], 1u);
        k = fkey(vb.y); if ((k >> 21) == pfx) atomicAdd(&sh[(k >> 10) & 2047u], 1u);
        k = fkey(vb.z); if ((k >> 21) == pfx) atomicAdd(&sh[(k >> 10) & 2047u], 1u);
        k = fkey(vb.w); if ((k >> 21) == pfx) atomicAdd(&sh[(k >> 10) & 2047u], 1u);
    }
    __syncthreads();
    for (int i2 = threadIdx.x; i2 < 2048; i2 += 256) {
        unsigned int v = sh[i2];
        if (v) atomicAdd(&g_h1[i2], v);
    }
    if (last_block(1, 1024u)) do_select(1, ks);
}

__global__ void k_hist2(const float* __restrict__ ks) {
    __shared__ unsigned int sh[1024];
    for (int i = threadIdx.x; i < 1024; i += 256) sh[i] = 0u;
    __syncthreads();
    const unsigned int pfx = g_pfx1;
    const float4* p = reinterpret_cast<const float4*>(g_xx);
    unsigned int i = blockIdx.x * 256u + threadIdx.x;
    const unsigned int stride = 1024u * 256u;
    for (int it = 0; it < 8; it++, i += 2u * stride) {
        float4 va = p[i];
        float4 vb = p[i + stride];        // both loads in flight (MLP=2)
        unsigned int k;
        k = fkey(va.x); if ((k >> 10) == pfx) atomicAdd(&sh[k & 1023u], 1u);
        k = fkey(va.y); if ((k >> 10) == pfx) atomicAdd(&sh[k & 1023u], 1u);
        k = fkey(va.z); if ((k >> 10) == pfx) atomicAdd(&sh[k & 1023u], 1u);
        k = fkey(va.w); if ((k >> 10) == pfx) atomicAdd(&sh[k & 1023u], 1u);
        k = fkey(vb.x); if ((k >> 10) == pfx) atomicAdd(&sh[k & 1023u], 1u);
        k = fkey(vb.y); if ((k >> 10) == pfx) atomicAdd(&sh[k & 1023u], 1u);
        k = fkey(vb.z); if ((k >> 10) == pfx) atomicAdd(&sh[k & 1023u], 1u);
        k = fkey(vb.w); if ((k >> 10) == pfx) atomicAdd(&sh[k & 1023u], 1u);
    }
    __syncthreads();
    for (int i2 = threadIdx.x; i2 < 1024; i2 += 256) {
        unsigned int v = sh[i2];
        if (v) atomicAdd(&g_h2[i2], v);
    }
    if (last_block(2, 1024u)) do_select(2, ks);
}

// Stage-A XLA row-reduction replica (bit-exact per-row shape). TWO rows per
// block: rows 2*bx, 2*bx+1. grid=(2048, 3).
__global__ void __launch_bounds__(256) k_rowreduce() {
    __shared__ float ws0[8];
    __shared__ float ws1[8];
    const int r0   = blockIdx.x * 2;
    const int r1   = r0 + 1;
    const int slot = blockIdx.y;
    const int diagskip = (slot != 2) ? 1 : 0;
    const int t = threadIdx.x;
    float s0 = g_par[0], s1 = g_par[1], s2 = g_par[2], s3 = g_par[3], s4 = g_par[4];
    const bool fast = g_par[5] > 0.5f;
    const float* M = mat_of(slot);
    const float2* p0 = reinterpret_cast<const float2*>(M + (long long)r0 * NROW);
    const float2* p1 = reinterpret_cast<const float2*>(M + (long long)r1 * NROW);

    float ax0 = 0.0f, ay0 = 0.0f, ax1 = 0.0f, ay1 = 0.0f;
    if (fast) {
#pragma unroll
        for (int i = 0; i < 8; i++) {
            float2 v0 = p0[i * 256 + t];
            float2 v1 = p1[i * 256 + t];
            int c = (i * 256 + t) * 2;
            float kx0 = kmean5f(v0.x, s0);
            float ky0 = kmean5f(v0.y, s0);
            float kx1 = kmean5f(v1.x, s0);
            float ky1 = kmean5f(v1.y, s0);
            if (diagskip && c == r0)     kx0 = 0.0f;
            if (diagskip && c + 1 == r0) ky0 = 0.0f;
            if (diagskip && c == r1)     kx1 = 0.0f;
            if (diagskip && c + 1 == r1) ky1 = 0.0f;
            ax0 += kx0; ay0 += ky0;
            ax1 += kx1; ay1 += ky1;
        }
    } else {
#pragma unroll
        for (int i = 0; i < 8; i++) {
            float2 v0 = p0[i * 256 + t];
            float2 v1 = p1[i * 256 + t];
            int c = (i * 256 + t) * 2;
            float kx0 = kmean5(v0.x, s0, s1, s2, s3, s4);
            float ky0 = kmean5(v0.y, s0, s1, s2, s3, s4);
            float kx1 = kmean5(v1.x, s0, s1, s2, s3, s4);
            float ky1 = kmean5(v1.y, s0, s1, s2, s3, s4);
            if (diagskip && c == r0)     kx0 = 0.0f;
            if (diagskip && c + 1 == r0) ky0 = 0.0f;
            if (diagskip && c == r1)     kx1 = 0.0f;
            if (diagskip && c + 1 == r1) ky1 = 0.0f;
            ax0 += kx0; ay0 += ky0;
            ax1 += kx1; ay1 += ky1;
        }
    }
    float v0 = ax0 + ay0;
    float v1 = ax1 + ay1;
#pragma unroll
    for (int o = 16; o > 0; o >>= 1) {
        v0 += __shfl_down_sync(0xffffffffu, v0, o);
        v1 += __shfl_down_sync(0xffffffffu, v1, o);
    }
    if ((t & 31) == 0) { ws0[t >> 5] = v0; ws1[t >> 5] = v1; }
    __syncthreads();
    if (t < 32) {
        float w = (t < 8) ? ws0[t] : 0.0f;
#pragma unroll
        for (int o = 16; o > 0; o >>= 1) w += __shfl_down_sync(0xffffffffu, w, o);
        if (t == 0) g_rows[slot][r0] = w;
    } else if (t < 64) {
        int l = t - 32;
        float w = (l < 8) ? ws1[l] : 0.0f;
#pragma unroll
        for (int o = 16; o > 0; o >>= 1) w += __shfl_down_sync(0xffffffffu, w, o);
        if (l == 0) g_rows[slot][r1] = w;
    }
}

// Stage-B + fused final combine: the last completing block does the combine.
__global__ void __launch_bounds__(256) k_stageB(float* out) {
    __shared__ float ws[8];
    const int slot = blockIdx.x;
    const int t = threadIdx.x;
    const float2* p = reinterpret_cast<const float2*>(g_rows[slot]);
    float ax = 0.0f, ay = 0.0f;
#pragma unroll
    for (int i = 0; i < 8; i++) {
        float2 v = p[i * 256 + t];
        ax += v.x;
        ay += v.y;
    }
    float v = ax + ay;
#pragma unroll
    for (int o = 16; o > 0; o >>= 1) v += __shfl_down_sync(0xffffffffu, v, o);
    if ((t & 31) == 0) ws[t >> 5] = v;
    __syncthreads();
    if (t < 32) {
        float w = (t < 8) ? ws[t] : 0.0f;
#pragma unroll
        for (int o = 16; o > 0; o >>= 1) w += __shfl_down_sync(0xffffffffu, w, o);
        if (t == 0) {
            g_S[slot] = w;
            __threadfence();
            unsigned int d = atomicAdd(&g_cnt[3], 1u);
            if (d == 2u) {   // last of 3 blocks: final combine
                float S1 = g_S[0], S2 = g_S[1], S3 = g_S[2];
                float od = (float)(1.0 / 16773120.0);   // 1/(4096*4095) f32
                float t1 = od * S1;
                float t2 = od * S2;
                float m3 = S3 * (1.0f / 16777216.0f);   // exact pow2 scale
                float t3 = 2.0f * m3;                   // exact
                out[0] = (t1 + t2) - t3;
            }
        }
    }
}

// ---------------- entry ----------------
extern "C" void kernel_launch(void* const* d_in, const int* in_sizes, int n_in,
                              void* d_out, int out_size) {
    (void)in_sizes; (void)n_in; (void)out_size;
    const float* x  = (const float*)d_in[0];
    const float* y  = (const float*)d_in[1];
    const float* ks = (const float*)d_in[2];

    const int TILE_SMEM = 2 * 128 * 69 * (int)sizeof(float);  // 70656 B dynamic
    cudaFuncSetAttribute(k_tile128, cudaFuncAttributeMaxDynamicSharedMemorySize,
                         TILE_SMEM);

    dim3 rn(512, 2);
    k_rownorm<<<rn, 256>>>(x, y);                 // init + row norms

    // 528 (xx tri, +hist0, +select0 in last block) + 528 (yy) + 1024 (zz)
    k_tile128<<<2080, 256, TILE_SMEM>>>(x, y, ks);

    k_hist1<<<1024, 256>>>(ks);                   // + select1 in last block
    k_hist2<<<1024, 256>>>(ks);                   // + select2 in last block

    dim3 rg(2048, 3);
    k_rowreduce<<<rg, 256>>>();                   // stage-A rows (2 rows/block)
    k_stageB<<<3, 256>>>((float*)d_out);          // stage-B + final combine
}

// round 17
// speedup vs baseline: 2.4507x; 1.0840x over previous
#include <cuda_runtime.h>
#include <math.h>

#define NROW 4096
#define DDIM 64

// ---------------- device scratch (no allocations allowed) ----------------
static __device__ float        g_xx[(long long)NROW * NROW];   // 64 MB dist(x,x)
static __device__ float        g_yy[(long long)NROW * NROW];   // 64 MB dist(y,y)
static __device__ float        g_zz[(long long)NROW * NROW];   // 64 MB dist(x,y)
static __device__ float        g_norms[2][NROW];               // row norms of x, y
static __device__ float        g_rows[3][NROW];                // stage-A f32 row sums
static __device__ float        g_S[3];                         // stage-B f32 sums
static __device__ unsigned int g_h0[2048];
static __device__ unsigned int g_h1[2048];
static __device__ unsigned int g_h2[1024];
static __device__ unsigned int g_pfx0, g_pfx1, g_rank;
static __device__ unsigned int g_cnt[4];   // completion counters (tile, h1, h2, stageB)
static __device__ float        g_par[8];   // [0..4]=s_k, [5]=fast-chain flag

// device-side selector (never pass __device__ symbols from host code)
__device__ __forceinline__ float* mat_of(int slot) {
    return (slot == 0) ? g_xx : (slot == 1) ? g_yy : g_zz;
}

// ---------------- helpers ----------------
// Cephes-style minimax expf (~1 ulp). Proven: rel_err == 0.0 end-to-end.
__device__ __forceinline__ float my_exp(float x) {
    x = fmaxf(x, -87.0f);
    float z = floorf(fmaf(x, 1.44269504088896341f, 0.5f));
    float r = fmaf(z, -0.693359375f, x);
    r = fmaf(z, 2.12194440e-4f, r);
    int n = (int)z;
    float p = 1.9875691500e-4f;
    p = fmaf(p, r, 1.3981999507e-3f);
    p = fmaf(p, r, 8.3334519073e-3f);
    p = fmaf(p, r, 4.1665795894e-2f);
    p = fmaf(p, r, 1.6666665459e-1f);
    p = fmaf(p, r, 5.0000001201e-1f);
    float res = fmaf(p, r * r, r) + 1.0f;
    return res * __int_as_float((n + 127) << 23);
}

// Markstein correctly-rounded-constant-division by 5 (3 FMA-class ops,
// bias-free — proven rel_err == 0.0 in R16).
__device__ __forceinline__ float div5(float s) {
    float q0 = s * 0.2f;
    float e  = fmaf(-5.0f, q0, s);
    return fmaf(e, 0.2f, q0);
}

// exact-replica 5-exp kernel mean: ((((e0+e1)+e2)+e3)+e4) / 5
__device__ __forceinline__ float kmean5(float d, float s0, float s1, float s2,
                                        float s3, float s4) {
    float s = my_exp(d * s0);
    s = s + my_exp(d * s1);
    s = s + my_exp(d * s2);
    s = s + my_exp(d * s3);
    s = s + my_exp(d * s4);
    return div5(s);
}

// 1-exp squaring chain (valid when s_{k+1} == 2*s_k exactly).
// Error amplification 2/4/8/16 ulp on e1..e4 is zero-mean pseudo-random over
// distinct arguments; sigma on the 16.7M-sum ~1e-4 << 0.0625 bin margin.
__device__ __forceinline__ float kmean5f(float d, float s0) {
    float v  = d * s0;
    float e0 = my_exp(v);
    float e1 = e0 * e0;      // exp(2v)
    float e2 = e1 * e1;      // exp(4v)
    float e3 = e2 * e2;      // exp(8v)
    float e4 = e3 * e3;      // exp(16v)
    float s = e0 + e1;
    s = s + e2;
    s = s + e3;
    s = s + e4;
    return div5(s);
}

// monotone key transform for float radix select
__device__ __forceinline__ unsigned int fkey(float f) {
    unsigned int b = __float_as_uint(f);
    return b ^ ((b & 0x80000000u) ? 0xffffffffu : 0x80000000u);
}

// warp-aggregated shared histogram add (weighted)
__device__ __forceinline__ void haddw(unsigned int* sh, unsigned int bin,
                                      unsigned int w) {
    unsigned int m = __match_any_sync(0xffffffffu, bin);
    if ((int)(threadIdx.x & 31u) == (int)(__ffs(m) - 1))
        atomicAdd(&sh[bin], (unsigned int)__popc(m) * w);
}

// In-kernel radix-select step, executed by ONE 256-thread block (the last
// finisher of the producing kernel). Integer-only.
__device__ void do_select(int pass, const float* __restrict__ ks) {
    __shared__ unsigned int sel_sh[2048];
    __shared__ unsigned int sel_ps[256];
    const unsigned int* hist = (pass == 0) ? g_h0 : (pass == 1) ? g_h1 : g_h2;
    const int nbins = (pass == 2) ? 1024 : 2048;
    const int per   = nbins / 256;          // 8 or 4
    const int tid   = threadIdx.x;
    unsigned int s = 0;
    for (int i = 0; i < per; i++) {
        unsigned int v = hist[tid * per + i];
        sel_sh[tid * per + i] = v;
        s += v;
    }
    sel_ps[tid] = s;
    __syncthreads();
#pragma unroll
    for (int o = 1; o < 256; o <<= 1) {
        unsigned int v = sel_ps[tid] + ((tid >= o) ? sel_ps[tid - o] : 0u);
        __syncthreads();
        sel_ps[tid] = v;
        __syncthreads();
    }
    const unsigned int rank = g_rank;
    const unsigned int incl = sel_ps[tid];
    const unsigned int excl = incl - s;
    if (excl <= rank && rank < incl) {      // unique owner thread
        unsigned int cum = excl;
        int b = tid * per;
        while (cum + sel_sh[b] <= rank) { cum += sel_sh[b]; b++; }
        g_rank = rank - cum;
        if (pass == 0) {
            g_pfx0 = (unsigned int)b;
        } else if (pass == 1) {
            g_pfx1 = (g_pfx0 << 11) | (unsigned int)b;
        } else {
            unsigned int key  = (g_pfx1 << 10) | (unsigned int)b;
            unsigned int bits = (key & 0x80000000u) ? (key ^ 0x80000000u) : ~key;
            float med  = __uint_as_float(bits);
            float base = -1.0f / med;
            float p0 = base * ks[0], p1 = base * ks[1], p2 = base * ks[2];
            float p3 = base * ks[3], p4 = base * ks[4];
            g_par[0] = p0; g_par[1] = p1; g_par[2] = p2; g_par[3] = p3; g_par[4] = p4;
            bool fast = (p1 == 2.0f * p0) && (p2 == 2.0f * p1) &&
                        (p3 == 2.0f * p2) && (p4 == 2.0f * p3);
            g_par[5] = fast ? 1.0f : 0.0f;
        }
    }
}

// last-block detector: returns true (uniformly across the block) for the
// final block of the grid to pass this point.
__device__ bool last_block(int which, unsigned int total) {
    __shared__ unsigned int isl;
    __threadfence();
    __syncthreads();
    if (threadIdx.x == 0)
        isl = (atomicAdd(&g_cnt[which], 1u) == total - 1u) ? 1u : 0u;
    __syncthreads();
    return isl != 0u;
}

// ---------------- kernels ----------------
// merged init + row norms: blockIdx.y selects x (0) or y (1)
__global__ void k_rownorm(const float* __restrict__ x, const float* __restrict__ y) {
    if (blockIdx.x == 0 && blockIdx.y == 0) {
        int t = threadIdx.x;
        for (int i = t; i < 2048; i += 256) { g_h0[i] = 0u; g_h1[i] = 0u; }
        for (int i = t; i < 1024; i += 256) g_h2[i] = 0u;
        if (t == 0) {
            g_rank = 8388607u;  // (N*N - 1) / 2 : lower-median rank
            g_pfx0 = 0u; g_pfx1 = 0u;
            g_cnt[0] = 0u; g_cnt[1] = 0u; g_cnt[2] = 0u; g_cnt[3] = 0u;
        }
    }
    int which = blockIdx.y;
    const float* a = which ? y : x;
    int row  = blockIdx.x * 8 + (threadIdx.x >> 5);
    int lane = threadIdx.x & 31;
    float v0 = a[row * DDIM + lane];
    float v1 = a[row * DDIM + 32 + lane];
    float s  = v0 * v0 + v1 * v1;
#pragma unroll
    for (int o = 16; o > 0; o >>= 1) s += __shfl_down_sync(0xffffffffu, s, o);
    if (lane == 0) g_norms[which][row] = s;
}

// 128x128 tile, 256 threads, 8x8/thread, K=64. Symmetry-aware, bit-exact
// mirror for xx/yy off-diagonal blocks. xx blocks build the pass-0 median
// histogram (weight 2 on mirrored) — integer-exact. The LAST block of the
// grid additionally runs select pass 0.
// Linear grid: [0,528)=xx tri, [528,1056)=yy tri, [1056,2080)=zz full.
__global__ void __launch_bounds__(256, 2) k_tile128(const float* __restrict__ x,
                                                    const float* __restrict__ y,
                                                    const float* __restrict__ ks) {
    extern __shared__ float sm[];
    float* As = sm;             // [128][69]
    float* Bs = sm + 128 * 69;  // [128][69]
    __shared__ unsigned int sh_hist[2048];

    int idx = blockIdx.x;
    int z, bxb, byb;
    if (idx < 1056) {
        z = (idx < 528) ? 0 : 1;
        int t = idx - z * 528;
        int by = (int)((sqrtf(8.0f * (float)t + 1.0f) - 1.0f) * 0.5f);
        while (by * (by + 1) / 2 > t) by--;
        while ((by + 1) * (by + 2) / 2 <= t) by++;
        byb = by;
        bxb = t - by * (by + 1) / 2;     // bxb <= byb
    } else {
        z = 2;
        int t = idx - 1056;
        bxb = t & 31;
        byb = t >> 5;
    }

    const float* A = (z == 1) ? y : x;
    const float* B = (z == 0) ? x : y;
    const int anw = (z == 1) ? 1 : 0;
    const int bnw = (z == 0) ? 0 : 1;
    float* OUT = mat_of(z);

    const int bm  = byb * 128;
    const int bc  = bxb * 128;
    const int tid = threadIdx.x;

    if (z == 0) {
#pragma unroll
        for (int i = tid; i < 2048; i += 256) sh_hist[i] = 0u;
    }

    const float4* Ag = reinterpret_cast<const float4*>(A + (long long)bm * DDIM);
    const float4* Bg = reinterpret_cast<const float4*>(B + (long long)bc * DDIM);
#pragma unroll
    for (int i = tid; i < 2048; i += 256) {
        int row = i >> 4, f4 = i & 15;
        float4 va = Ag[row * 16 + f4];
        float4 vb = Bg[row * 16 + f4];
        int c4 = f4 * 4;
        As[row * 69 + c4 + 0] = va.x; As[row * 69 + c4 + 1] = va.y;
        As[row * 69 + c4 + 2] = va.z; As[row * 69 + c4 + 3] = va.w;
        Bs[row * 69 + c4 + 0] = vb.x; Bs[row * 69 + c4 + 1] = vb.y;
        Bs[row * 69 + c4 + 2] = vb.z; Bs[row * 69 + c4 + 3] = vb.w;
    }
    __syncthreads();

    const int tx = tid & 15, ty = tid >> 4;

    int arow[8], brow[8];
#pragma unroll
    for (int i = 0; i < 8; i++) arow[i] = (ty + 16 * i) * 69;
#pragma unroll
    for (int j = 0; j < 8; j++)
        brow[j] = (2 * tx + 32 * (j >> 1) + (j & 1)) * 69;

    float acc[8][8];
#pragma unroll
    for (int i = 0; i < 8; i++)
#pragma unroll
        for (int j = 0; j < 8; j++) acc[i][j] = 0.0f;

    float a0[8], b0[8], a1[8], b1[8];
#pragma unroll
    for (int i = 0; i < 8; i++) a0[i] = As[arow[i]];
#pragma unroll
    for (int j = 0; j < 8; j++) b0[j] = Bs[brow[j]];

#pragma unroll 4
    for (int k = 0; k < 64; k += 2) {
#pragma unroll
        for (int i = 0; i < 8; i++) a1[i] = As[arow[i] + k + 1];
#pragma unroll
        for (int j = 0; j < 8; j++) b1[j] = Bs[brow[j] + k + 1];
#pragma unroll
        for (int i = 0; i < 8; i++)
#pragma unroll
            for (int j = 0; j < 8; j++)
                acc[i][j] = fmaf(a0[i], b0[j], acc[i][j]);
#pragma unroll
        for (int i = 0; i < 8; i++) a0[i] = As[arow[i] + k + 2];  // k=62 -> pad col
#pragma unroll
        for (int j = 0; j < 8; j++) b0[j] = Bs[brow[j] + k + 2];
#pragma unroll
        for (int i = 0; i < 8; i++)
#pragma unroll
            for (int j = 0; j < 8; j++)
                acc[i][j] = fmaf(a1[i], b1[j], acc[i][j]);
    }

    const float* an = g_norms[anw];
    const float* bn = g_norms[bnw];
    const bool mirror = (z < 2) && (bm != bc);
    const unsigned int hw = mirror ? 2u : 1u;   // hist weight (xx only)
    float* T = sm;  // transposed staging [128][129] — reuses As/Bs space

    if (mirror) __syncthreads();   // k-loop smem reads complete before overwrite

#pragma unroll
    for (int i = 0; i < 8; i++) {
        int rl = ty + 16 * i;
        int r  = bm + rl;
        float base2 = an[r];
#pragma unroll
        for (int h = 0; h < 4; h++) {
            int cl = 2 * tx + 32 * h;
            int c  = bc + cl;
            float2 o;
            o.x = fmaf(-2.0f, acc[i][2 * h + 0], base2 + bn[c + 0]);
            o.y = fmaf(-2.0f, acc[i][2 * h + 1], base2 + bn[c + 1]);
            *reinterpret_cast<float2*>(&OUT[(long long)r * NROW + c]) = o;
            if (mirror) {
                T[(cl + 0) * 129 + rl] = o.x;   // conflict-free: bank=2tx+ty(+1)
                T[(cl + 1) * 129 + rl] = o.y;
            }
            if (z == 0) {
                haddw(sh_hist, fkey(o.x) >> 21, hw);
                haddw(sh_hist, fkey(o.y) >> 21, hw);
            }
        }
    }

    if (mirror) {
        __syncthreads();
        int rr   = tid >> 1;
        int cb   = (tid & 1) * 64;
        long long obase = (long long)(bc + rr) * NROW + bm + cb;
#pragma unroll
        for (int v = 0; v < 16; v++) {
            float4 o;
            o.x = T[rr * 129 + cb + 4 * v + 0];
            o.y = T[rr * 129 + cb + 4 * v + 1];
            o.z = T[rr * 129 + cb + 4 * v + 2];
            o.w = T[rr * 129 + cb + 4 * v + 3];
            *reinterpret_cast<float4*>(&OUT[obase + 4 * v]) = o;
        }
    }

    if (z == 0) {
        __syncthreads();   // all hadds done
#pragma unroll
        for (int i = tid; i < 2048; i += 256) {
            unsigned int v = sh_hist[i];
            if (v) atomicAdd(&g_h0[i], v);
        }
    }

    // last block of the whole grid runs select pass 0
    if (last_block(0, 2080u)) do_select(0, ks);
}

// ---- radix-select passes 1 & 2: MLP-2 sweeps; last block runs the select ----
__global__ void k_hist1(const float* __restrict__ ks) {
    __shared__ unsigned int sh[2048];
    for (int i = threadIdx.x; i < 2048; i += 256) sh[i] = 0u;
    __syncthreads();
    const unsigned int pfx = g_pfx0;
    const float4* p = reinterpret_cast<const float4*>(g_xx);
    unsigned int i = blockIdx.x * 256u + threadIdx.x;
    const unsigned int stride = 1024u * 256u;
    for (int it = 0; it < 8; it++, i += 2u * stride) {
        float4 va = p[i];
        float4 vb = p[i + stride];        // both loads in flight (MLP=2)
        unsigned int k;
        k = fkey(va.x); if ((k >> 21) == pfx) atomicAdd(&sh[(k >> 10) & 2047u], 1u);
        k = fkey(va.y); if ((k >> 21) == pfx) atomicAdd(&sh[(k >> 10) & 2047u], 1u);
        k = fkey(va.z); if ((k >> 21) == pfx) atomicAdd(&sh[(k >> 10) & 2047u], 1u);
        k = fkey(va.w); if ((k >> 21) == pfx) atomicAdd(&sh[(k >> 10) & 2047u], 1u);
        k = fkey(vb.x); if ((k >> 21) == pfx) atomicAdd(&sh[(k >> 10) & 2047u], 1u);
        k = fkey(vb.y); if ((k >> 21) == pfx) atomicAdd(&sh[(k >> 10) & 2047u], 1u);
        k = fkey(vb.z); if ((k >> 21) == pfx) atomicAdd(&sh[(k >> 10) & 2047u], 1u);
        k = fkey(vb.w); if ((k >> 21) == pfx) atomicAdd(&sh[(k >> 10) & 2047u], 1u);
    }
    __syncthreads();
    for (int i2 = threadIdx.x; i2 < 2048; i2 += 256) {
        unsigned int v = sh[i2];
        if (v) atomicAdd(&g_h1[i2], v);
    }
    if (last_block(1, 1024u)) do_select(1, ks);
}

__global__ void k_hist2(const float* __restrict__ ks) {
    __shared__ unsigned int sh[1024];
    for (int i = threadIdx.x; i < 1024; i += 256) sh[i] = 0u;
    __syncthreads();
    const unsigned int pfx = g_pfx1;
    const float4* p = reinterpret_cast<const float4*>(g_xx);
    unsigned int i = blockIdx.x * 256u + threadIdx.x;
    const unsigned int stride = 1024u * 256u;
    for (int it = 0; it < 8; it++, i += 2u * stride) {
        float4 va = p[i];
        float4 vb = p[i + stride];        // both loads in flight (MLP=2)
        unsigned int k;
        k = fkey(va.x); if ((k >> 10) == pfx) atomicAdd(&sh[k & 1023u], 1u);
        k = fkey(va.y); if ((k >> 10) == pfx) atomicAdd(&sh[k & 1023u], 1u);
        k = fkey(va.z); if ((k >> 10) == pfx) atomicAdd(&sh[k & 1023u], 1u);
        k = fkey(va.w); if ((k >> 10) == pfx) atomicAdd(&sh[k & 1023u], 1u);
        k = fkey(vb.x); if ((k >> 10) == pfx) atomicAdd(&sh[k & 1023u], 1u);
        k = fkey(vb.y); if ((k >> 10) == pfx) atomicAdd(&sh[k & 1023u], 1u);
        k = fkey(vb.z); if ((k >> 10) == pfx) atomicAdd(&sh[k & 1023u], 1u);
        k = fkey(vb.w); if ((k >> 10) == pfx) atomicAdd(&sh[k & 1023u], 1u);
    }
    __syncthreads();
    for (int i2 = threadIdx.x; i2 < 1024; i2 += 256) {
        unsigned int v = sh[i2];
        if (v) atomicAdd(&g_h2[i2], v);
    }
    if (last_block(2, 1024u)) do_select(2, ks);
}

// Stage-A XLA row-reduction replica (bit-exact per-row shape). TWO rows per
// block: rows 2*bx, 2*bx+1. grid=(2048, 3).
__global__ void __launch_bounds__(256) k_rowreduce() {
    __shared__ float ws0[8];
    __shared__ float ws1[8];
    const int r0   = blockIdx.x * 2;
    const int r1   = r0 + 1;
    const int slot = blockIdx.y;
    const int diagskip = (slot != 2) ? 1 : 0;
    const int t = threadIdx.x;
    float s0 = g_par[0], s1 = g_par[1], s2 = g_par[2], s3 = g_par[3], s4 = g_par[4];
    const bool fast = g_par[5] > 0.5f;
    const float* M = mat_of(slot);
    const float2* p0 = reinterpret_cast<const float2*>(M + (long long)r0 * NROW);
    const float2* p1 = reinterpret_cast<const float2*>(M + (long long)r1 * NROW);

    float ax0 = 0.0f, ay0 = 0.0f, ax1 = 0.0f, ay1 = 0.0f;
    if (fast) {
#pragma unroll
        for (int i = 0; i < 8; i++) {
            float2 v0 = p0[i * 256 + t];
            float2 v1 = p1[i * 256 + t];
            int c = (i * 256 + t) * 2;
            float kx0 = kmean5f(v0.x, s0);
            float ky0 = kmean5f(v0.y, s0);
            float kx1 = kmean5f(v1.x, s0);
            float ky1 = kmean5f(v1.y, s0);
            if (diagskip && c == r0)     kx0 = 0.0f;
            if (diagskip && c + 1 == r0) ky0 = 0.0f;
            if (diagskip && c == r1)     kx1 = 0.0f;
            if (diagskip && c + 1 == r1) ky1 = 0.0f;
            ax0 += kx0; ay0 += ky0;
            ax1 += kx1; ay1 += ky1;
        }
    } else {
#pragma unroll
        for (int i = 0; i < 8; i++) {
            float2 v0 = p0[i * 256 + t];
            float2 v1 = p1[i * 256 + t];
            int c = (i * 256 + t) * 2;
            float kx0 = kmean5(v0.x, s0, s1, s2, s3, s4);
            float ky0 = kmean5(v0.y, s0, s1, s2, s3, s4);
            float kx1 = kmean5(v1.x, s0, s1, s2, s3, s4);
            float ky1 = kmean5(v1.y, s0, s1, s2, s3, s4);
            if (diagskip && c == r0)     kx0 = 0.0f;
            if (diagskip && c + 1 == r0) ky0 = 0.0f;
            if (diagskip && c == r1)     kx1 = 0.0f;
            if (diagskip && c + 1 == r1) ky1 = 0.0f;
            ax0 += kx0; ay0 += ky0;
            ax1 += kx1; ay1 += ky1;
        }
    }
    float v0 = ax0 + ay0;
    float v1 = ax1 + ay1;
#pragma unroll
    for (int o = 16; o > 0; o >>= 1) {
        v0 += __shfl_down_sync(0xffffffffu, v0, o);
        v1 += __shfl_down_sync(0xffffffffu, v1, o);
    }
    if ((t & 31) == 0) { ws0[t >> 5] = v0; ws1[t >> 5] = v1; }
    __syncthreads();
    if (t < 32) {
        float w = (t < 8) ? ws0[t] : 0.0f;
#pragma unroll
        for (int o = 16; o > 0; o >>= 1) w += __shfl_down_sync(0xffffffffu, w, o);
        if (t == 0) g_rows[slot][r0] = w;
    } else if (t < 64) {
        int l = t - 32;
        float w = (l < 8) ? ws1[l] : 0.0f;
#pragma unroll
        for (int o = 16; o > 0; o >>= 1) w += __shfl_down_sync(0xffffffffu, w, o);
        if (l == 0) g_rows[slot][r1] = w;
    }
}

// Stage-B + fused final combine: the last completing block does the combine.
__global__ void __launch_bounds__(256) k_stageB(float* out) {
    __shared__ float ws[8];
    const int slot = blockIdx.x;
    const int t = threadIdx.x;
    const float2* p = reinterpret_cast<const float2*>(g_rows[slot]);
    float ax = 0.0f, ay = 0.0f;
#pragma unroll
    for (int i = 0; i < 8; i++) {
        float2 v = p[i * 256 + t];
        ax += v.x;
        ay += v.y;
    }
    float v = ax + ay;
#pragma unroll
    for (int o = 16; o > 0; o >>= 1) v += __shfl_down_sync(0xffffffffu, v, o);
    if ((t & 31) == 0) ws[t >> 5] = v;
    __syncthreads();
    if (t < 32) {
        float w = (t < 8) ? ws[t] : 0.0f;
#pragma unroll
        for (int o = 16; o > 0; o >>= 1) w += __shfl_down_sync(0xffffffffu, w, o);
        if (t == 0) {
            g_S[slot] = w;
            __threadfence();
            unsigned int d = atomicAdd(&g_cnt[3], 1u);
            if (d == 2u) {   // last of 3 blocks: final combine
                float S1 = g_S[0], S2 = g_S[1], S3 = g_S[2];
                float od = (float)(1.0 / 16773120.0);   // 1/(4096*4095) f32
                float t1 = od * S1;
                float t2 = od * S2;
                float m3 = S3 * (1.0f / 16777216.0f);   // exact pow2 scale
                float t3 = 2.0f * m3;                   // exact
                out[0] = (t1 + t2) - t3;
            }
        }
    }
}

// ---------------- entry ----------------
extern "C" void kernel_launch(void* const* d_in, const int* in_sizes, int n_in,
                              void* d_out, int out_size) {
    (void)in_sizes; (void)n_in; (void)out_size;
    const float* x  = (const float*)d_in[0];
    const float* y  = (const float*)d_in[1];
    const float* ks = (const float*)d_in[2];

    const int TILE_SMEM = 2 * 128 * 69 * (int)sizeof(float);  // 70656 B dynamic
    cudaFuncSetAttribute(k_tile128, cudaFuncAttributeMaxDynamicSharedMemorySize,
                         TILE_SMEM);

    dim3 rn(512, 2);
    k_rownorm<<<rn, 256>>>(x, y);                 // init + row norms

    // 528 (xx tri, +hist0, +select0 in last block) + 528 (yy) + 1024 (zz)
    k_tile128<<<2080, 256, TILE_SMEM>>>(x, y, ks);

    k_hist1<<<1024, 256>>>(ks);                   // + select1 in last block
    k_hist2<<<1024, 256>>>(ks);                   // + select2 in last block

    dim3 rg(2048, 3);
    k_rowreduce<<<rg, 256>>>();                   // stage-A rows (2 rows/block)
    k_stageB<<<3, 256>>>((float*)d_out);          // stage-B + final combine
}